// round 1
// baseline (speedup 1.0000x reference)
#include <cuda_runtime.h>
#include <cuda_bf16.h>
#include <math.h>

// Problem constants
#define BB 4
#define SS 2048
#define DD 1024
#define HH 16
#define HD 64
#define BS (BB*SS)      // 8192 rows for the projection GEMMs

// ---------------------------------------------------------------------------
// Static device scratch (alloc-free rule): q,k,v in [B,H,S,HD], attn in [B,S,D]
// ---------------------------------------------------------------------------
__device__ float g_q[(size_t)BB*HH*SS*HD];
__device__ float g_k[(size_t)BB*HH*SS*HD];
__device__ float g_v[(size_t)BB*HH*SS*HD];
__device__ float g_attn[(size_t)BB*SS*DD];

// ---------------------------------------------------------------------------
// GEMM: C[m][n] = sum_k A[m][k] * W[n][k] + bias[n]
// A: [M=8192, K=1024] row-major, W: [N=1024, K=1024] row-major.
// head_major==1: write to [B,H,S,HD] layout; else plain [M,N].
// 128x128 block tile, BK=8, 8x8 per thread, 256 threads.
// ---------------------------------------------------------------------------
__global__ __launch_bounds__(256) void gemm_nt_kernel(
    const float* __restrict__ A, const float* __restrict__ W,
    const float* __restrict__ bias, float* __restrict__ C, int head_major)
{
    __shared__ float As[8][128];
    __shared__ float Ws[8][128];

    const int tid = threadIdx.x;
    const int tx = tid & 15;
    const int ty = tid >> 4;
    const int m0 = blockIdx.y * 128;
    const int n0 = blockIdx.x * 128;

    const int lr = tid >> 1;         // 0..127
    const int lc = (tid & 1) * 4;    // 0 or 4

    const float* Aptr = A + (size_t)(m0 + lr) * DD + lc;
    const float* Wptr = W + (size_t)(n0 + lr) * DD + lc;

    float acc[8][8];
    #pragma unroll
    for (int i = 0; i < 8; i++)
        #pragma unroll
        for (int j = 0; j < 8; j++) acc[i][j] = 0.f;

    for (int k0 = 0; k0 < DD; k0 += 8) {
        float4 av = *(const float4*)(Aptr + k0);
        float4 wv = *(const float4*)(Wptr + k0);
        __syncthreads();
        As[lc+0][lr] = av.x; As[lc+1][lr] = av.y; As[lc+2][lr] = av.z; As[lc+3][lr] = av.w;
        Ws[lc+0][lr] = wv.x; Ws[lc+1][lr] = wv.y; Ws[lc+2][lr] = wv.z; Ws[lc+3][lr] = wv.w;
        __syncthreads();
        #pragma unroll
        for (int kk = 0; kk < 8; kk++) {
            float ar[8], br[8];
            *(float4*)&ar[0] = *(const float4*)&As[kk][ty*8];
            *(float4*)&ar[4] = *(const float4*)&As[kk][ty*8+4];
            *(float4*)&br[0] = *(const float4*)&Ws[kk][tx*8];
            *(float4*)&br[4] = *(const float4*)&Ws[kk][tx*8+4];
            #pragma unroll
            for (int i = 0; i < 8; i++)
                #pragma unroll
                for (int j = 0; j < 8; j++)
                    acc[i][j] = fmaf(ar[i], br[j], acc[i][j]);
        }
    }

    #pragma unroll
    for (int i = 0; i < 8; i++) {
        const int gm = m0 + ty*8 + i;
        const int b  = gm >> 11;         // /2048
        const int s  = gm & 2047;
        #pragma unroll
        for (int j = 0; j < 8; j++) {
            const int gn = n0 + tx*8 + j;
            const float v = acc[i][j] + bias[gn];
            if (head_major) {
                const int h = gn >> 6;
                const int d = gn & 63;
                g_dummy_noop:
                C[(((size_t)b*HH + h)*SS + s)*HD + d] = v;
            } else {
                C[(size_t)gm*DD + gn] = v;
            }
        }
    }
}

// ---------------------------------------------------------------------------
// RoPE in place on [B,H,S,HD] tensor. One thread per (b,h,s,d<32) pair.
// ---------------------------------------------------------------------------
__global__ __launch_bounds__(256) void rope_kernel(
    float* __restrict__ t, const float* __restrict__ cosb, const float* __restrict__ sinb)
{
    const int idx = blockIdx.x * blockDim.x + threadIdx.x;   // < B*H*S*32
    const int d   = idx & 31;
    const int bhs = idx >> 5;
    const int s   = bhs & (SS - 1);
    const size_t base = (size_t)bhs * HD;

    const float x1 = t[base + d];
    const float x2 = t[base + d + 32];
    const float c1 = cosb[s*HD + d],      s1 = sinb[s*HD + d];
    const float c2 = cosb[s*HD + d + 32], s2 = sinb[s*HD + d + 32];
    t[base + d]      = x1*c1 - x2*s1;   // rotated = -x2 for first half
    t[base + d + 32] = x2*c2 + x1*s2;   // rotated = +x1 for second half
}

// ---------------------------------------------------------------------------
// Flash attention (causal) fp32. One block per (q-tile of 64, b*h).
// 256 threads. Kt/Qt transposed in smem for the score GEMM; Vs natural.
// Online softmax: thread t owns row r=t>>2, 16 of 64 output dims.
// Writes output directly in [B,S,D] layout.
// ---------------------------------------------------------------------------
#define PS_STRIDE 65
#define SMEM_ATTN ((3*64*64 + 64*PS_STRIDE) * (int)sizeof(float))

__global__ __launch_bounds__(256) void attn_kernel(
    const float* __restrict__ Q, const float* __restrict__ K,
    const float* __restrict__ V, float* __restrict__ Out)
{
    extern __shared__ float sm[];
    float* Qt = sm;              // [64][64], Qt[d][i]
    float* Kt = sm + 64*64;      // [64][64], Kt[d][j]
    float* Vs = sm + 2*64*64;    // [64][64], Vs[j][d]
    float* Ps = sm + 3*64*64;    // [64][PS_STRIDE]

    const int tid = threadIdx.x;
    const int qt  = blockIdx.x;          // 0..31
    const int bh  = blockIdx.y;          // 0..63
    const int q0  = qt * 64;
    const size_t head_base = (size_t)bh * SS * HD;

    // Load Q tile transposed
    {
        const int i = tid >> 2;
        const int c = (tid & 3) * 16;
        #pragma unroll
        for (int u = 0; u < 16; u += 4) {
            float4 v = *(const float4*)&Q[head_base + (size_t)(q0 + i)*HD + c + u];
            Qt[(c+u+0)*64 + i] = v.x;
            Qt[(c+u+1)*64 + i] = v.y;
            Qt[(c+u+2)*64 + i] = v.z;
            Qt[(c+u+3)*64 + i] = v.w;
        }
    }

    const int tx   = tid & 15;
    const int ty   = tid >> 4;
    const int r    = tid >> 2;       // softmax/PV row
    const int part = tid & 3;
    const int db   = part * 16;      // output-dim base
    const int jb   = part * 16;      // score-column segment

    float O[16];
    #pragma unroll
    for (int u = 0; u < 16; u++) O[u] = 0.f;
    float m_prev = -1e30f, l_sum = 0.f;

    for (int kt = 0; kt <= qt; kt++) {
        const int k0 = kt * 64;
        __syncthreads();   // Qt ready (first iter) / prev iter PV done
        // Load K transposed + V natural
        {
            const int j = tid >> 2;
            const int c = (tid & 3) * 16;
            #pragma unroll
            for (int u = 0; u < 16; u += 4) {
                float4 kv = *(const float4*)&K[head_base + (size_t)(k0 + j)*HD + c + u];
                Kt[(c+u+0)*64 + j] = kv.x;
                Kt[(c+u+1)*64 + j] = kv.y;
                Kt[(c+u+2)*64 + j] = kv.z;
                Kt[(c+u+3)*64 + j] = kv.w;
                *(float4*)&Vs[j*64 + c + u] =
                    *(const float4*)&V[head_base + (size_t)(k0 + j)*HD + c + u];
            }
        }
        __syncthreads();

        // Score tile: 4x4 per thread over 16x16 thread grid
        float acc[4][4];
        #pragma unroll
        for (int i = 0; i < 4; i++)
            #pragma unroll
            for (int j = 0; j < 4; j++) acc[i][j] = 0.f;

        #pragma unroll 8
        for (int d = 0; d < 64; d++) {
            float4 qv = *(const float4*)&Qt[d*64 + ty*4];
            float4 kv = *(const float4*)&Kt[d*64 + tx*4];
            float qr[4] = {qv.x, qv.y, qv.z, qv.w};
            float kr[4] = {kv.x, kv.y, kv.z, kv.w};
            #pragma unroll
            for (int i = 0; i < 4; i++)
                #pragma unroll
                for (int j = 0; j < 4; j++)
                    acc[i][j] = fmaf(qr[i], kr[j], acc[i][j]);
        }

        const float scale = 0.125f;  // HD^-0.5
        const bool diag = (kt == qt);
        #pragma unroll
        for (int i = 0; i < 4; i++)
            #pragma unroll
            for (int j = 0; j < 4; j++) {
                float v = acc[i][j] * scale;
                if (diag && (tx*4 + j) > (ty*4 + i)) v = -1e30f;
                Ps[(ty*4 + i)*PS_STRIDE + tx*4 + j] = v;
            }
        __syncthreads();

        // Online softmax on row r, segment jb..jb+16
        float pv[16];
        float mloc = -1e30f;
        #pragma unroll
        for (int u = 0; u < 16; u++) {
            pv[u] = Ps[r*PS_STRIDE + jb + u];
            mloc = fmaxf(mloc, pv[u]);
        }
        mloc = fmaxf(mloc, __shfl_xor_sync(0xffffffffu, mloc, 1));
        mloc = fmaxf(mloc, __shfl_xor_sync(0xffffffffu, mloc, 2));
        const float mnew = fmaxf(m_prev, mloc);
        float lloc = 0.f;
        #pragma unroll
        for (int u = 0; u < 16; u++) {
            float p = __expf(pv[u] - mnew);
            Ps[r*PS_STRIDE + jb + u] = p;
            lloc += p;
        }
        lloc += __shfl_xor_sync(0xffffffffu, lloc, 1);
        lloc += __shfl_xor_sync(0xffffffffu, lloc, 2);
        const float alpha = __expf(m_prev - mnew);
        l_sum = l_sum * alpha + lloc;
        m_prev = mnew;
        #pragma unroll
        for (int u = 0; u < 16; u++) O[u] *= alpha;
        __syncwarp();   // group's Ps row writes visible (same warp)

        // PV: O[r][db..db+16) += sum_j P[r][j] * V[j][db..]
        #pragma unroll 4
        for (int j = 0; j < 64; j++) {
            const float p = Ps[r*PS_STRIDE + j];
            float4 v0 = *(const float4*)&Vs[j*64 + db];
            float4 v1 = *(const float4*)&Vs[j*64 + db + 4];
            float4 v2 = *(const float4*)&Vs[j*64 + db + 8];
            float4 v3 = *(const float4*)&Vs[j*64 + db + 12];
            O[0]  = fmaf(p, v0.x, O[0]);  O[1]  = fmaf(p, v0.y, O[1]);
            O[2]  = fmaf(p, v0.z, O[2]);  O[3]  = fmaf(p, v0.w, O[3]);
            O[4]  = fmaf(p, v1.x, O[4]);  O[5]  = fmaf(p, v1.y, O[5]);
            O[6]  = fmaf(p, v1.z, O[6]);  O[7]  = fmaf(p, v1.w, O[7]);
            O[8]  = fmaf(p, v2.x, O[8]);  O[9]  = fmaf(p, v2.y, O[9]);
            O[10] = fmaf(p, v2.z, O[10]); O[11] = fmaf(p, v2.w, O[11]);
            O[12] = fmaf(p, v3.x, O[12]); O[13] = fmaf(p, v3.y, O[13]);
            O[14] = fmaf(p, v3.z, O[14]); O[15] = fmaf(p, v3.w, O[15]);
        }
    }

    // Epilogue: normalize, write to [B,S,D]
    const float inv = 1.f / l_sum;
    #pragma unroll
    for (int u = 0; u < 16; u++) O[u] *= inv;
    const int b = bh >> 4;
    const int h = bh & 15;
    const size_t o = ((size_t)(b*SS + q0 + r))*DD + h*HD + db;
    *(float4*)&Out[o+0]  = make_float4(O[0],  O[1],  O[2],  O[3]);
    *(float4*)&Out[o+4]  = make_float4(O[4],  O[5],  O[6],  O[7]);
    *(float4*)&Out[o+8]  = make_float4(O[8],  O[9],  O[10], O[11]);
    *(float4*)&Out[o+12] = make_float4(O[12], O[13], O[14], O[15]);
}

// ---------------------------------------------------------------------------
// Launch
// ---------------------------------------------------------------------------
extern "C" void kernel_launch(void* const* d_in, const int* in_sizes, int n_in,
                              void* d_out, int out_size)
{
    const float* x    = (const float*)d_in[0];
    const float* cosb = (const float*)d_in[1];
    const float* sinb = (const float*)d_in[2];
    // d_in[3] = attn_mask (causal; handled analytically)
    const float* Wq = (const float*)d_in[4];
    const float* bq = (const float*)d_in[5];
    const float* Wk = (const float*)d_in[6];
    const float* bk = (const float*)d_in[7];
    const float* Wv = (const float*)d_in[8];
    const float* bv = (const float*)d_in[9];
    const float* Wo = (const float*)d_in[10];
    const float* bo = (const float*)d_in[11];
    float* out = (float*)d_out;

    float *q, *k, *v, *attn;
    cudaGetSymbolAddress((void**)&q,    g_q);
    cudaGetSymbolAddress((void**)&k,    g_k);
    cudaGetSymbolAddress((void**)&v,    g_v);
    cudaGetSymbolAddress((void**)&attn, g_attn);

    cudaFuncSetAttribute(attn_kernel,
                         cudaFuncAttributeMaxDynamicSharedMemorySize, SMEM_ATTN);

    dim3 ggrid(DD/128, BS/128);    // (8, 64)
    gemm_nt_kernel<<<ggrid, 256>>>(x, Wq, bq, q, 1);
    gemm_nt_kernel<<<ggrid, 256>>>(x, Wk, bk, k, 1);
    gemm_nt_kernel<<<ggrid, 256>>>(x, Wv, bv, v, 1);

    const int rope_threads = BB*HH*SS*32;
    rope_kernel<<<rope_threads/256, 256>>>(q, cosb, sinb);
    rope_kernel<<<rope_threads/256, 256>>>(k, cosb, sinb);

    attn_kernel<<<dim3(SS/64, BB*HH), 256, SMEM_ATTN>>>(q, k, v, attn);

    gemm_nt_kernel<<<ggrid, 256>>>(attn, Wo, bo, out, 0);
}

// round 4
// speedup vs baseline: 4.4932x; 4.4932x over previous
#include <cuda_runtime.h>
#include <cuda_bf16.h>
#include <math.h>
#include <stdint.h>

// Problem constants
#define BB 4
#define SS 2048
#define DD 1024
#define HH 16
#define HD 64
#define BS (BB*SS)          // 8192 rows for projection GEMMs
#define NQ (BB*HH*SS*HD)    // 8388608 elements per q/k/v tensor
#define NX (BS*DD)          // 8388608 elements for x / attn
#define NW (DD*DD)          // 1048576 per weight

// ---------------------------------------------------------------------------
// Static device scratch
// ---------------------------------------------------------------------------
__device__ float g_q[NQ];
__device__ float g_k[NQ];
__device__ float g_v[NQ];
__device__ float g_attn[NX];

__device__ __nv_bfloat16 g_xhi[NX],  g_xlo[NX];
__device__ __nv_bfloat16 g_ahi[NX],  g_alo[NX];
__device__ __nv_bfloat16 g_qhi[NQ],  g_qlo[NQ];
__device__ __nv_bfloat16 g_khi[NQ],  g_klo[NQ];
__device__ __nv_bfloat16 g_vthi[NQ], g_vtlo[NQ];   // [B,H,HD,S] transposed
__device__ __nv_bfloat16 g_wh[4][NW], g_wl[4][NW];

// ---------------------------------------------------------------------------
// helpers
// ---------------------------------------------------------------------------
__device__ __forceinline__ uint32_t pack_bf2(float a, float b) {
    __nv_bfloat16 ha = __float2bfloat16(a), hb = __float2bfloat16(b);
    unsigned short ua = *reinterpret_cast<unsigned short*>(&ha);
    unsigned short ub = *reinterpret_cast<unsigned short*>(&hb);
    return (uint32_t)ua | ((uint32_t)ub << 16);
}
__device__ __forceinline__ float bf_res(float x) {
    __nv_bfloat16 h = __float2bfloat16(x);
    return x - __bfloat162float(h);
}

// bf16 mma m16n8k16: D += A(16x16 row) * B(16x8 col)
__device__ __forceinline__ void mma_bf16(float* c, const uint32_t* a,
                                         uint32_t b0, uint32_t b1)
{
    asm("mma.sync.aligned.m16n8k16.row.col.f32.bf16.bf16.f32 "
        "{%0,%1,%2,%3},{%4,%5,%6,%7},{%8,%9},{%0,%1,%2,%3};"
        : "+f"(c[0]), "+f"(c[1]), "+f"(c[2]), "+f"(c[3])
        : "r"(a[0]), "r"(a[1]), "r"(a[2]), "r"(a[3]), "r"(b0), "r"(b1));
}

#define CP16(dst_smem_u32, src_gptr) \
    asm volatile("cp.async.ca.shared.global [%0], [%1], 16;\n" \
                 :: "r"(dst_smem_u32), "l"(src_gptr))
#define CP_COMMIT() asm volatile("cp.async.commit_group;\n")
#define CP_WAIT1()  asm volatile("cp.async.wait_group 1;\n")
#define CP_WAIT0()  asm volatile("cp.async.wait_group 0;\n")

// ---------------------------------------------------------------------------
// split fp32 -> bf16 hi/lo (vectorized by 4)
// ---------------------------------------------------------------------------
__global__ __launch_bounds__(256) void split4_kernel(
    const float* __restrict__ in, __nv_bfloat16* __restrict__ hi,
    __nv_bfloat16* __restrict__ lo, int n4)
{
    int i = blockIdx.x * blockDim.x + threadIdx.x;
    if (i >= n4) return;
    float4 v = ((const float4*)in)[i];
    ((uint2*)hi)[i] = make_uint2(pack_bf2(v.x, v.y), pack_bf2(v.z, v.w));
    ((uint2*)lo)[i] = make_uint2(pack_bf2(bf_res(v.x), bf_res(v.y)),
                                 pack_bf2(bf_res(v.z), bf_res(v.w)));
}

// ---------------------------------------------------------------------------
// RoPE + split: read fp32 [B,H,S,HD], write rotated bf16 hi/lo same layout
// ---------------------------------------------------------------------------
__global__ __launch_bounds__(256) void rope_split_kernel(
    const float* __restrict__ t, const float* __restrict__ cosb,
    const float* __restrict__ sinb,
    __nv_bfloat16* __restrict__ hi, __nv_bfloat16* __restrict__ lo)
{
    const int idx = blockIdx.x * blockDim.x + threadIdx.x;  // < B*H*S*32
    const int d   = idx & 31;
    const int bhs = idx >> 5;
    const int s   = bhs & (SS - 1);
    const size_t base = (size_t)bhs * HD;

    const float x1 = t[base + d];
    const float x2 = t[base + d + 32];
    const float c1 = cosb[s*HD + d],      s1 = sinb[s*HD + d];
    const float c2 = cosb[s*HD + d + 32], s2 = sinb[s*HD + d + 32];
    const float o1 = x1*c1 - x2*s1;
    const float o2 = x2*c2 + x1*s2;
    hi[base + d]      = __float2bfloat16(o1);
    lo[base + d]      = __float2bfloat16(bf_res(o1));
    hi[base + d + 32] = __float2bfloat16(o2);
    lo[base + d + 32] = __float2bfloat16(bf_res(o2));
}

// ---------------------------------------------------------------------------
// V transpose + split: [B,H,S,HD] fp32 -> [B,H,HD,S] bf16 hi/lo
// ---------------------------------------------------------------------------
__global__ __launch_bounds__(256) void vtrans_split_kernel(
    const float* __restrict__ v,
    __nv_bfloat16* __restrict__ thi, __nv_bfloat16* __restrict__ tlo)
{
    __shared__ float tile[64][65];
    const int tid = threadIdx.x;
    const int s0  = blockIdx.x * 64;
    const int bh  = blockIdx.y;
    const size_t base_in  = ((size_t)bh * SS + s0) * HD;
    const size_t base_out = (size_t)bh * HD * SS;

    #pragma unroll
    for (int i = 0; i < 16; i++) {
        int c = tid + 256*i;            // 4096 elements
        int srow = c >> 6, d = c & 63;
        tile[srow][d] = v[base_in + (size_t)srow*HD + d];
    }
    __syncthreads();
    #pragma unroll
    for (int i = 0; i < 16; i++) {
        int c = tid + 256*i;
        int drow = c >> 6, scol = c & 63;
        float val = tile[scol][drow];
        thi[base_out + (size_t)drow*SS + s0 + scol] = __float2bfloat16(val);
        tlo[base_out + (size_t)drow*SS + s0 + scol] = __float2bfloat16(bf_res(val));
    }
}

// ---------------------------------------------------------------------------
// GEMM (bf16x3): C[m][n] = sum_k A[m][k]*W[n][k] + bias[n]
// A hi/lo: [M,1024] bf16, W hi/lo: [1024,1024] bf16, C fp32.
// 128x128 tile, BK=32, 8 warps, 2-stage cp.async.
// ---------------------------------------------------------------------------
#define RST 20                  // u32 per smem row (16 data + 4 pad)
#define OPB (128*RST)           // u32 per operand-stage = 2560
#define GEMM_SMEM (8*OPB*4)     // 81920 B

__global__ __launch_bounds__(256, 2) void gemm_bf3_kernel(
    const __nv_bfloat16* __restrict__ Ah, const __nv_bfloat16* __restrict__ Al,
    const __nv_bfloat16* __restrict__ Wh, const __nv_bfloat16* __restrict__ Wl,
    const float* __restrict__ bias, float* __restrict__ C, int head_major)
{
    extern __shared__ uint32_t su[];
    // per stage: [Ah | Al | Wh | Wl]
    const int tid  = threadIdx.x;
    const int m0   = blockIdx.y * 128;
    const int n0   = blockIdx.x * 128;
    const int w    = tid >> 5;
    const int lane = tid & 31;
    const int g    = lane >> 2;
    const int q    = lane & 3;
    const int wm   = (w & 3) * 32;
    const int wn   = (w >> 2) * 64;

    float acc[2][8][4];
    #pragma unroll
    for (int mt = 0; mt < 2; mt++)
        #pragma unroll
        for (int nt = 0; nt < 8; nt++)
            #pragma unroll
            for (int r = 0; r < 4; r++) acc[mt][nt][r] = 0.f;

    const int NK = DD / 32;

    // loader: 512 chunks (16B) per operand, 2 per thread per operand
    #define LOAD_STAGE(kt, stg) do {                                          \
        uint32_t* base = su + (stg)*4*OPB;                                    \
        _Pragma("unroll")                                                     \
        for (int i_ = 0; i_ < 2; i_++) {                                      \
            int c_ = tid + 256*i_;                                            \
            int row_ = c_ >> 2, col16_ = c_ & 3;                              \
            uint32_t so_ = (uint32_t)__cvta_generic_to_shared(                \
                &base[row_*RST + col16_*4]);                                  \
            size_t ga_ = (size_t)(m0+row_)*DD + (kt)*32 + col16_*8;           \
            size_t gw_ = (size_t)(n0+row_)*DD + (kt)*32 + col16_*8;           \
            CP16(so_,           Ah + ga_);                                    \
            CP16(so_ + OPB*4,   Al + ga_);                                    \
            CP16(so_ + 2*OPB*4, Wh + gw_);                                    \
            CP16(so_ + 3*OPB*4, Wl + gw_);                                    \
        }                                                                     \
        CP_COMMIT();                                                          \
    } while (0)

    LOAD_STAGE(0, 0);

    for (int it = 0; it < NK; it++) {
        if (it + 1 < NK) {
            LOAD_STAGE(it + 1, (it + 1) & 1);
            CP_WAIT1();
        } else {
            CP_WAIT0();
        }
        __syncthreads();

        const uint32_t* AhS = su + (it & 1)*4*OPB;
        const uint32_t* AlS = AhS + OPB;
        const uint32_t* WhS = AhS + 2*OPB;
        const uint32_t* WlS = AhS + 3*OPB;

        #pragma unroll
        for (int s16 = 0; s16 < 2; s16++) {
            const int kb = s16 * 8;
            uint32_t ah[2][4], al[2][4];
            #pragma unroll
            for (int mt = 0; mt < 2; mt++) {
                const int rb = wm + mt*16;
                ah[mt][0] = AhS[(rb + g    )*RST + kb + q    ];
                ah[mt][1] = AhS[(rb + g + 8)*RST + kb + q    ];
                ah[mt][2] = AhS[(rb + g    )*RST + kb + q + 4];
                ah[mt][3] = AhS[(rb + g + 8)*RST + kb + q + 4];
                al[mt][0] = AlS[(rb + g    )*RST + kb + q    ];
                al[mt][1] = AlS[(rb + g + 8)*RST + kb + q    ];
                al[mt][2] = AlS[(rb + g    )*RST + kb + q + 4];
                al[mt][3] = AlS[(rb + g + 8)*RST + kb + q + 4];
            }
            #pragma unroll
            for (int nt = 0; nt < 8; nt++) {
                const int rw = (wn + nt*8 + g)*RST + kb;
                const uint32_t bh0 = WhS[rw + q], bh1 = WhS[rw + q + 4];
                const uint32_t bl0 = WlS[rw + q], bl1 = WlS[rw + q + 4];
                #pragma unroll
                for (int mt = 0; mt < 2; mt++) {
                    mma_bf16(acc[mt][nt], ah[mt], bh0, bh1);
                    mma_bf16(acc[mt][nt], ah[mt], bl0, bl1);
                    mma_bf16(acc[mt][nt], al[mt], bh0, bh1);
                }
            }
        }
        __syncthreads();
    }
    #undef LOAD_STAGE

    // epilogue
    #pragma unroll
    for (int mt = 0; mt < 2; mt++) {
        const int row0 = m0 + wm + mt*16 + g;
        const int row1 = row0 + 8;
        #pragma unroll
        for (int nt = 0; nt < 8; nt++) {
            const int col = n0 + wn + nt*8 + 2*q;
            const float b0 = bias[col], b1 = bias[col + 1];
            const float v00 = acc[mt][nt][0] + b0, v01 = acc[mt][nt][1] + b1;
            const float v10 = acc[mt][nt][2] + b0, v11 = acc[mt][nt][3] + b1;
            if (head_major) {
                const int h = col >> 6, d = col & 63;
                const int b_0 = row0 >> 11, s_0 = row0 & 2047;
                const int b_1 = row1 >> 11, s_1 = row1 & 2047;
                *(float2*)&C[(((size_t)b_0*HH + h)*SS + s_0)*HD + d] = make_float2(v00, v01);
                *(float2*)&C[(((size_t)b_1*HH + h)*SS + s_1)*HD + d] = make_float2(v10, v11);
            } else {
                *(float2*)&C[(size_t)row0*DD + col] = make_float2(v00, v01);
                *(float2*)&C[(size_t)row1*DD + col] = make_float2(v10, v11);
            }
        }
    }
}

// ---------------------------------------------------------------------------
// FlashAttention-2 (causal), bf16x3. 4 warps, 64 q-rows/block, KV tiles 64.
// Q,K: [B,H,S,HD] bf16 hi/lo.  Vt: [B,H,HD,S] bf16 hi/lo.  Out fp32 [B,S,D].
// ---------------------------------------------------------------------------
#define KST 36                       // u32 per 64-half smem row (32 data + 4 pad)
#define ATTN_SMEM (6*64*KST*4)       // 55296 B

__global__ __launch_bounds__(128) void attn_bf3_kernel(
    const __nv_bfloat16* __restrict__ Qh, const __nv_bfloat16* __restrict__ Ql,
    const __nv_bfloat16* __restrict__ Kh, const __nv_bfloat16* __restrict__ Kl,
    const __nv_bfloat16* __restrict__ Vth, const __nv_bfloat16* __restrict__ Vtl,
    float* __restrict__ Out)
{
    extern __shared__ uint32_t su[];
    uint32_t* PsH = su;               // Q hi tile, then P hi
    uint32_t* PsL = su + 64*KST;      // Q lo tile, then P lo
    uint32_t* KsH = su + 2*64*KST;
    uint32_t* KsL = su + 3*64*KST;
    uint32_t* VsH = su + 4*64*KST;    // Vt tile [d][key]
    uint32_t* VsL = su + 5*64*KST;

    const int tid  = threadIdx.x;
    const int w    = tid >> 5;
    const int lane = tid & 31;
    const int g    = lane >> 2;
    const int q    = lane & 3;
    const int qt   = (SS/64 - 1) - blockIdx.x;
    const int bh   = blockIdx.y;
    const int q0   = qt * 64;
    const size_t hb = (size_t)bh * SS * HD;

    // load Q hi/lo tiles (64 rows x 64 halves)
    #pragma unroll
    for (int i = 0; i < 4; i++) {
        int c = tid + 128*i;          // 512 chunks
        int row = c >> 3, col16 = c & 7;
        size_t go = hb + (size_t)(q0 + row)*HD + col16*8;
        *(uint4*)&PsH[row*KST + col16*4] = *(const uint4*)(Qh + go);
        *(uint4*)&PsL[row*KST + col16*4] = *(const uint4*)(Ql + go);
    }
    __syncthreads();

    // preload Q fragments
    uint32_t rQh[4][4], rQl[4][4];
    const int rb = 16*w;
    #pragma unroll
    for (int k = 0; k < 4; k++) {
        const int kb = k*8;
        rQh[k][0] = PsH[(rb + g    )*KST + kb + q    ];
        rQh[k][1] = PsH[(rb + g + 8)*KST + kb + q    ];
        rQh[k][2] = PsH[(rb + g    )*KST + kb + q + 4];
        rQh[k][3] = PsH[(rb + g + 8)*KST + kb + q + 4];
        rQl[k][0] = PsL[(rb + g    )*KST + kb + q    ];
        rQl[k][1] = PsL[(rb + g + 8)*KST + kb + q    ];
        rQl[k][2] = PsL[(rb + g    )*KST + kb + q + 4];
        rQl[k][3] = PsL[(rb + g + 8)*KST + kb + q + 4];
    }

    float oc[8][4];
    #pragma unroll
    for (int nt = 0; nt < 8; nt++)
        #pragma unroll
        for (int r = 0; r < 4; r++) oc[nt][r] = 0.f;
    float m0 = -1e30f, m1 = -1e30f, l0 = 0.f, l1 = 0.f;

    const int row0g = q0 + 16*w + g;
    const int row1g = row0g + 8;

    for (int kt = 0; kt <= qt; kt++) {
        const int k0 = kt * 64;
        __syncthreads();   // prev iter K/V reads done (1st iter: Q frag reads done)

        // load K hi/lo and Vt hi/lo tiles
        #pragma unroll
        for (int i = 0; i < 4; i++) {
            int c = tid + 128*i;
            int row = c >> 3, col16 = c & 7;
            size_t ko = hb + (size_t)(k0 + row)*HD + col16*8;
            *(uint4*)&KsH[row*KST + col16*4] = *(const uint4*)(Kh + ko);
            *(uint4*)&KsL[row*KST + col16*4] = *(const uint4*)(Kl + ko);
            size_t vo = ((size_t)bh*HD + row)*SS + k0 + col16*8;
            *(uint4*)&VsH[row*KST + col16*4] = *(const uint4*)(Vth + vo);
            *(uint4*)&VsL[row*KST + col16*4] = *(const uint4*)(Vtl + vo);
        }
        __syncthreads();

        // scores (bf16x3)
        float sc[8][4];
        #pragma unroll
        for (int nt = 0; nt < 8; nt++)
            #pragma unroll
            for (int r = 0; r < 4; r++) sc[nt][r] = 0.f;

        #pragma unroll
        for (int k = 0; k < 4; k++) {
            const int kb = k*8;
            #pragma unroll
            for (int nt = 0; nt < 8; nt++) {
                const int rw = (nt*8 + g)*KST + kb;
                const uint32_t bh0 = KsH[rw + q], bh1 = KsH[rw + q + 4];
                const uint32_t bl0 = KsL[rw + q], bl1 = KsL[rw + q + 4];
                mma_bf16(sc[nt], rQh[k], bh0, bh1);
                mma_bf16(sc[nt], rQh[k], bl0, bl1);
                mma_bf16(sc[nt], rQl[k], bh0, bh1);
            }
        }

        // scale + causal mask
        const float scale = 0.125f;
        const bool diag = (kt == qt);
        #pragma unroll
        for (int nt = 0; nt < 8; nt++) {
            const int colb = k0 + nt*8 + 2*q;
            #pragma unroll
            for (int j = 0; j < 2; j++) {
                float v0 = sc[nt][j]   * scale;
                float v1 = sc[nt][2+j] * scale;
                if (diag && (colb + j) > row0g) v0 = -1e30f;
                if (diag && (colb + j) > row1g) v1 = -1e30f;
                sc[nt][j]   = v0;
                sc[nt][2+j] = v1;
            }
        }

        // online softmax
        float mx0 = -1e30f, mx1 = -1e30f;
        #pragma unroll
        for (int nt = 0; nt < 8; nt++) {
            mx0 = fmaxf(mx0, fmaxf(sc[nt][0], sc[nt][1]));
            mx1 = fmaxf(mx1, fmaxf(sc[nt][2], sc[nt][3]));
        }
        mx0 = fmaxf(mx0, __shfl_xor_sync(0xffffffffu, mx0, 1));
        mx0 = fmaxf(mx0, __shfl_xor_sync(0xffffffffu, mx0, 2));
        mx1 = fmaxf(mx1, __shfl_xor_sync(0xffffffffu, mx1, 1));
        mx1 = fmaxf(mx1, __shfl_xor_sync(0xffffffffu, mx1, 2));
        const float mn0 = fmaxf(m0, mx0);
        const float mn1 = fmaxf(m1, mx1);
        const float a0 = __expf(m0 - mn0);
        const float a1 = __expf(m1 - mn1);
        m0 = mn0; m1 = mn1;

        float s0 = 0.f, s1 = 0.f;
        #pragma unroll
        for (int nt = 0; nt < 8; nt++) {
            float p00 = __expf(sc[nt][0] - mn0);
            float p01 = __expf(sc[nt][1] - mn0);
            float p10 = __expf(sc[nt][2] - mn1);
            float p11 = __expf(sc[nt][3] - mn1);
            s0 += p00 + p01;
            s1 += p10 + p11;
            PsH[(rb + g    )*KST + nt*4 + q] = pack_bf2(p00, p01);
            PsL[(rb + g    )*KST + nt*4 + q] = pack_bf2(bf_res(p00), bf_res(p01));
            PsH[(rb + g + 8)*KST + nt*4 + q] = pack_bf2(p10, p11);
            PsL[(rb + g + 8)*KST + nt*4 + q] = pack_bf2(bf_res(p10), bf_res(p11));
        }
        s0 += __shfl_xor_sync(0xffffffffu, s0, 1);
        s0 += __shfl_xor_sync(0xffffffffu, s0, 2);
        s1 += __shfl_xor_sync(0xffffffffu, s1, 1);
        s1 += __shfl_xor_sync(0xffffffffu, s1, 2);
        l0 = l0*a0 + s0;
        l1 = l1*a1 + s1;
        #pragma unroll
        for (int nt = 0; nt < 8; nt++) {
            oc[nt][0] *= a0; oc[nt][1] *= a0;
            oc[nt][2] *= a1; oc[nt][3] *= a1;
        }
        __syncwarp();   // P rows are warp-private: make writes visible

        // PV (bf16x3): O += P(16x64) . Vt^T
        #pragma unroll
        for (int k = 0; k < 4; k++) {
            const int kb = k*8;
            uint32_t ah[4], al[4];
            ah[0] = PsH[(rb + g    )*KST + kb + q    ];
            ah[1] = PsH[(rb + g + 8)*KST + kb + q    ];
            ah[2] = PsH[(rb + g    )*KST + kb + q + 4];
            ah[3] = PsH[(rb + g + 8)*KST + kb + q + 4];
            al[0] = PsL[(rb + g    )*KST + kb + q    ];
            al[1] = PsL[(rb + g + 8)*KST + kb + q    ];
            al[2] = PsL[(rb + g    )*KST + kb + q + 4];
            al[3] = PsL[(rb + g + 8)*KST + kb + q + 4];
            #pragma unroll
            for (int nt = 0; nt < 8; nt++) {
                const int rw = (nt*8 + g)*KST + kb;
                const uint32_t bh0 = VsH[rw + q], bh1 = VsH[rw + q + 4];
                const uint32_t bl0 = VsL[rw + q], bl1 = VsL[rw + q + 4];
                mma_bf16(oc[nt], ah, bh0, bh1);
                mma_bf16(oc[nt], ah, bl0, bl1);
                mma_bf16(oc[nt], al, bh0, bh1);
            }
        }
        __syncwarp();   // P reads done before next iter rewrites
    }

    // epilogue: normalize + write [B,S,D]
    const float i0 = 1.f / l0;
    const float i1 = 1.f / l1;
    const int b = bh >> 4;
    const int h = bh & 15;
    const size_t o0 = ((size_t)(b*SS + row0g))*DD + h*HD;
    const size_t o1 = ((size_t)(b*SS + row1g))*DD + h*HD;
    #pragma unroll
    for (int nt = 0; nt < 8; nt++) {
        const int col = nt*8 + 2*q;
        *(float2*)&Out[o0 + col] = make_float2(oc[nt][0]*i0, oc[nt][1]*i0);
        *(float2*)&Out[o1 + col] = make_float2(oc[nt][2]*i1, oc[nt][3]*i1);
    }
}

// ---------------------------------------------------------------------------
// Launch
// ---------------------------------------------------------------------------
extern "C" void kernel_launch(void* const* d_in, const int* in_sizes, int n_in,
                              void* d_out, int out_size)
{
    const float* x    = (const float*)d_in[0];
    const float* cosb = (const float*)d_in[1];
    const float* sinb = (const float*)d_in[2];
    // d_in[3] = attn_mask (causal; handled analytically)
    const float* Wq = (const float*)d_in[4];
    const float* bq = (const float*)d_in[5];
    const float* Wk = (const float*)d_in[6];
    const float* bk = (const float*)d_in[7];
    const float* Wv = (const float*)d_in[8];
    const float* bv = (const float*)d_in[9];
    const float* Wo = (const float*)d_in[10];
    const float* bo = (const float*)d_in[11];
    float* out = (float*)d_out;

    float *qp, *kp, *vp, *attn;
    __nv_bfloat16 *xhi, *xlo, *ahi, *alo, *qhi, *qlo, *khi, *klo, *vthi, *vtlo;
    __nv_bfloat16 *wh, *wl;
    cudaGetSymbolAddress((void**)&qp,   g_q);
    cudaGetSymbolAddress((void**)&kp,   g_k);
    cudaGetSymbolAddress((void**)&vp,   g_v);
    cudaGetSymbolAddress((void**)&attn, g_attn);
    cudaGetSymbolAddress((void**)&xhi,  g_xhi);
    cudaGetSymbolAddress((void**)&xlo,  g_xlo);
    cudaGetSymbolAddress((void**)&ahi,  g_ahi);
    cudaGetSymbolAddress((void**)&alo,  g_alo);
    cudaGetSymbolAddress((void**)&qhi,  g_qhi);
    cudaGetSymbolAddress((void**)&qlo,  g_qlo);
    cudaGetSymbolAddress((void**)&khi,  g_khi);
    cudaGetSymbolAddress((void**)&klo,  g_klo);
    cudaGetSymbolAddress((void**)&vthi, g_vthi);
    cudaGetSymbolAddress((void**)&vtlo, g_vtlo);
    cudaGetSymbolAddress((void**)&wh,   g_wh);
    cudaGetSymbolAddress((void**)&wl,   g_wl);

    cudaFuncSetAttribute(gemm_bf3_kernel,
                         cudaFuncAttributeMaxDynamicSharedMemorySize, GEMM_SMEM);
    cudaFuncSetAttribute(attn_bf3_kernel,
                         cudaFuncAttributeMaxDynamicSharedMemorySize, ATTN_SMEM);

    // splits
    split4_kernel<<<NX/4/256, 256>>>(x, xhi, xlo, NX/4);
    split4_kernel<<<NW/4/256, 256>>>(Wq, wh + 0*(size_t)NW, wl + 0*(size_t)NW, NW/4);
    split4_kernel<<<NW/4/256, 256>>>(Wk, wh + 1*(size_t)NW, wl + 1*(size_t)NW, NW/4);
    split4_kernel<<<NW/4/256, 256>>>(Wv, wh + 2*(size_t)NW, wl + 2*(size_t)NW, NW/4);
    split4_kernel<<<NW/4/256, 256>>>(Wo, wh + 3*(size_t)NW, wl + 3*(size_t)NW, NW/4);

    // projections (fp32 out, head-major)
    dim3 ggrid(DD/128, BS/128);
    gemm_bf3_kernel<<<ggrid, 256, GEMM_SMEM>>>(xhi, xlo, wh + 0*(size_t)NW, wl + 0*(size_t)NW, bq, qp, 1);
    gemm_bf3_kernel<<<ggrid, 256, GEMM_SMEM>>>(xhi, xlo, wh + 1*(size_t)NW, wl + 1*(size_t)NW, bk, kp, 1);
    gemm_bf3_kernel<<<ggrid, 256, GEMM_SMEM>>>(xhi, xlo, wh + 2*(size_t)NW, wl + 2*(size_t)NW, bv, vp, 1);

    // rope + split / transpose + split
    const int rope_threads = BB*HH*SS*32;
    rope_split_kernel<<<rope_threads/256, 256>>>(qp, cosb, sinb, qhi, qlo);
    rope_split_kernel<<<rope_threads/256, 256>>>(kp, cosb, sinb, khi, klo);
    vtrans_split_kernel<<<dim3(SS/64, BB*HH), 256>>>(vp, vthi, vtlo);

    // attention
    attn_bf3_kernel<<<dim3(SS/64, BB*HH), 128, ATTN_SMEM>>>(
        qhi, qlo, khi, klo, vthi, vtlo, attn);

    // output projection
    split4_kernel<<<NX/4/256, 256>>>(attn, ahi, alo, NX/4);
    gemm_bf3_kernel<<<ggrid, 256, GEMM_SMEM>>>(ahi, alo, wh + 3*(size_t)NW, wl + 3*(size_t)NW, bo, out, 0);
}

// round 6
// speedup vs baseline: 5.1349x; 1.1428x over previous
#include <cuda_runtime.h>
#include <cuda_bf16.h>
#include <stdint.h>

// Problem constants
#define BB 4
#define SS 2048
#define DD 1024
#define HH 16
#define HD 64
#define BS (BB*SS)
#define NQ (BB*HH*SS*HD)
#define NX (BS*DD)
#define NW (DD*DD)

// ---------------------------------------------------------------------------
// Static device scratch
// ---------------------------------------------------------------------------
__device__ float g_v[NQ];                             // V fp32 head-major
__device__ __nv_bfloat16 g_xhi[NX],  g_xlo[NX];
__device__ __nv_bfloat16 g_ahi[NX],  g_alo[NX];       // attention out hi/lo
__device__ __nv_bfloat16 g_qhi[NQ],  g_qlo[NQ];
__device__ __nv_bfloat16 g_khi[NQ],  g_klo[NQ];
__device__ __nv_bfloat16 g_vthi[NQ], g_vtlo[NQ];      // [B,H,HD,S]
__device__ __nv_bfloat16 g_wh[4][NW], g_wl[4][NW];

// ---------------------------------------------------------------------------
// helpers
// ---------------------------------------------------------------------------
__device__ __forceinline__ uint32_t pack_bf2(float a, float b) {
    __nv_bfloat16 ha = __float2bfloat16(a), hb = __float2bfloat16(b);
    unsigned short ua = *reinterpret_cast<unsigned short*>(&ha);
    unsigned short ub = *reinterpret_cast<unsigned short*>(&hb);
    return (uint32_t)ua | ((uint32_t)ub << 16);
}
__device__ __forceinline__ float bf_res(float x) {
    __nv_bfloat16 h = __float2bfloat16(x);
    return x - __bfloat162float(h);
}

__device__ __forceinline__ void mma_bf16(float* c, const uint32_t* a,
                                         uint32_t b0, uint32_t b1)
{
    asm("mma.sync.aligned.m16n8k16.row.col.f32.bf16.bf16.f32 "
        "{%0,%1,%2,%3},{%4,%5,%6,%7},{%8,%9},{%0,%1,%2,%3};"
        : "+f"(c[0]), "+f"(c[1]), "+f"(c[2]), "+f"(c[3])
        : "r"(a[0]), "r"(a[1]), "r"(a[2]), "r"(a[3]), "r"(b0), "r"(b1));
}

__device__ __forceinline__ void ldsm_x4(uint32_t* r, uint32_t addr) {
    asm volatile("ldmatrix.sync.aligned.m8n8.x4.shared.b16 {%0,%1,%2,%3}, [%4];"
        : "=r"(r[0]), "=r"(r[1]), "=r"(r[2]), "=r"(r[3]) : "r"(addr));
}

#define CP16(dst_smem_u32, src_gptr) \
    asm volatile("cp.async.cg.shared.global [%0], [%1], 16;\n" \
                 :: "r"(dst_smem_u32), "l"(src_gptr))
#define CP_COMMIT() asm volatile("cp.async.commit_group;\n")
#define CP_WAIT1()  asm volatile("cp.async.wait_group 1;\n")
#define CP_WAIT0()  asm volatile("cp.async.wait_group 0;\n")

// ---------------------------------------------------------------------------
// split fp32 -> bf16 hi/lo
// ---------------------------------------------------------------------------
__global__ __launch_bounds__(256) void split4_kernel(
    const float* __restrict__ in, __nv_bfloat16* __restrict__ hi,
    __nv_bfloat16* __restrict__ lo, int n4)
{
    int i = blockIdx.x * blockDim.x + threadIdx.x;
    if (i >= n4) return;
    float4 v = ((const float4*)in)[i];
    ((uint2*)hi)[i] = make_uint2(pack_bf2(v.x, v.y), pack_bf2(v.z, v.w));
    ((uint2*)lo)[i] = make_uint2(pack_bf2(bf_res(v.x), bf_res(v.y)),
                                 pack_bf2(bf_res(v.z), bf_res(v.w)));
}

// ---------------------------------------------------------------------------
// V transpose + split: [B,H,S,HD] fp32 -> [B,H,HD,S] bf16 hi/lo
// ---------------------------------------------------------------------------
__global__ __launch_bounds__(256) void vtrans_split_kernel(
    const float* __restrict__ v,
    __nv_bfloat16* __restrict__ thi, __nv_bfloat16* __restrict__ tlo)
{
    __shared__ float tile[64][65];
    const int tid = threadIdx.x;
    const int s0  = blockIdx.x * 64;
    const int bh  = blockIdx.y;
    const size_t base_in  = ((size_t)bh * SS + s0) * HD;
    const size_t base_out = (size_t)bh * HD * SS;

    #pragma unroll
    for (int i = 0; i < 16; i++) {
        int c = tid + 256*i;
        int srow = c >> 6, d = c & 63;
        tile[srow][d] = v[base_in + (size_t)srow*HD + d];
    }
    __syncthreads();
    #pragma unroll
    for (int i = 0; i < 16; i++) {
        int c = tid + 256*i;
        int drow = c >> 6, scol = c & 63;
        float val = tile[scol][drow];
        thi[base_out + (size_t)drow*SS + s0 + scol] = __float2bfloat16(val);
        tlo[base_out + (size_t)drow*SS + s0 + scol] = __float2bfloat16(bf_res(val));
    }
}

// ---------------------------------------------------------------------------
// GEMM (bf16x3, ldmatrix): C = A.W^T + bias
// mode 0: plain fp32 out [M,N]
// mode 1: head-major fp32 out [B,H,S,HD]
// mode 2: head-major + rope, bf16 hi/lo out
// ---------------------------------------------------------------------------
#define RST 20                  // u32 per smem row (16 data + 4 pad) = 80B
#define OPB (128*RST)
#define GEMM_SMEM (8*OPB*4)     // 81920 B

__global__ __launch_bounds__(256, 2) void gemm_bf3_kernel(
    const __nv_bfloat16* __restrict__ Ah, const __nv_bfloat16* __restrict__ Al,
    const __nv_bfloat16* __restrict__ Wh, const __nv_bfloat16* __restrict__ Wl,
    const float* __restrict__ bias, const float* __restrict__ cosb,
    const float* __restrict__ sinb, float* __restrict__ Cf,
    __nv_bfloat16* __restrict__ Chi, __nv_bfloat16* __restrict__ Clo, int mode)
{
    extern __shared__ uint32_t su[];
    const uint32_t smb = (uint32_t)__cvta_generic_to_shared(su);

    const int tid  = threadIdx.x;
    const int m0   = blockIdx.y * 128;
    const int n0   = blockIdx.x * 128;
    const int w    = tid >> 5;
    const int lane = tid & 31;
    const int g    = lane >> 2;
    const int q    = lane & 3;
    const int wm   = (w & 3) * 32;
    const int wn   = (w >> 2) * 64;

    // ldmatrix per-lane byte offsets
    const uint32_t aoff = (uint32_t)(((((lane>>3)&1)*8 + (lane&7))*RST + ((lane>>4)*4)) * 4);
    const uint32_t boff = (uint32_t)((((lane>>4)*8 + (lane&7))*RST + (((lane>>3)&1)*4)) * 4);

    float acc[2][8][4];
    #pragma unroll
    for (int mt = 0; mt < 2; mt++)
        #pragma unroll
        for (int nt = 0; nt < 8; nt++)
            #pragma unroll
            for (int r = 0; r < 4; r++) acc[mt][nt][r] = 0.f;

    const int NK = DD / 32;

    #define LOAD_STAGE(kt, stg) do {                                          \
        uint32_t sb_ = smb + (stg)*4*OPB*4;                                   \
        _Pragma("unroll")                                                     \
        for (int i_ = 0; i_ < 2; i_++) {                                      \
            int c_ = tid + 256*i_;                                            \
            int row_ = c_ >> 2, col16_ = c_ & 3;                              \
            uint32_t so_ = sb_ + (uint32_t)((row_*RST + col16_*4)*4);         \
            size_t ga_ = (size_t)(m0+row_)*DD + (kt)*32 + col16_*8;           \
            size_t gw_ = (size_t)(n0+row_)*DD + (kt)*32 + col16_*8;           \
            CP16(so_,           Ah + ga_);                                    \
            CP16(so_ + OPB*4,   Al + ga_);                                    \
            CP16(so_ + 2*OPB*4, Wh + gw_);                                    \
            CP16(so_ + 3*OPB*4, Wl + gw_);                                    \
        }                                                                     \
        CP_COMMIT();                                                          \
    } while (0)

    LOAD_STAGE(0, 0);

    for (int it = 0; it < NK; it++) {
        if (it + 1 < NK) {
            LOAD_STAGE(it + 1, (it + 1) & 1);
            CP_WAIT1();
        } else {
            CP_WAIT0();
        }
        __syncthreads();

        const uint32_t sb  = smb + (it & 1)*4*OPB*4;
        const uint32_t ahB = sb;
        const uint32_t alB = sb + OPB*4;
        const uint32_t whB = sb + 2*OPB*4;
        const uint32_t wlB = sb + 3*OPB*4;

        #pragma unroll
        for (int s16 = 0; s16 < 2; s16++) {
            const uint32_t kbyte = s16 * 32;     // 8 u32 per k16 step
            uint32_t ah[2][4], al[2][4];
            #pragma unroll
            for (int mt = 0; mt < 2; mt++) {
                const uint32_t ro = (uint32_t)((wm + mt*16)*RST*4);
                ldsm_x4(ah[mt], ahB + aoff + ro + kbyte);
                ldsm_x4(al[mt], alB + aoff + ro + kbyte);
            }
            #pragma unroll
            for (int ntp = 0; ntp < 4; ntp++) {
                const uint32_t ro = (uint32_t)((wn + ntp*16)*RST*4);
                uint32_t wh4[4], wl4[4];
                ldsm_x4(wh4, whB + boff + ro + kbyte);
                ldsm_x4(wl4, wlB + boff + ro + kbyte);
                #pragma unroll
                for (int j = 0; j < 2; j++) {
                    const int nt = 2*ntp + j;
                    const uint32_t bh0 = wh4[2*j], bh1 = wh4[2*j+1];
                    const uint32_t bl0 = wl4[2*j], bl1 = wl4[2*j+1];
                    #pragma unroll
                    for (int mt = 0; mt < 2; mt++) {
                        mma_bf16(acc[mt][nt], ah[mt], bh0, bh1);
                        mma_bf16(acc[mt][nt], ah[mt], bl0, bl1);
                        mma_bf16(acc[mt][nt], al[mt], bh0, bh1);
                    }
                }
            }
        }
        __syncthreads();
    }
    #undef LOAD_STAGE

    // epilogue
    if (mode == 2) {
        // rope + split, head-major bf16 hi/lo
        uint32_t* HI = (uint32_t*)Chi;
        uint32_t* LO = (uint32_t*)Clo;
        #pragma unroll
        for (int mt = 0; mt < 2; mt++) {
            const int row0 = m0 + wm + mt*16 + g;
            #pragma unroll
            for (int nt = 0; nt < 4; nt++) {
                const int col = n0 + wn + nt*8 + 2*q;   // d in [0,32), even
                const int d = col & 63, h = col >> 6;
                const float bi10 = bias[col],    bi11 = bias[col+1];
                const float bi20 = bias[col+32], bi21 = bias[col+33];
                #pragma unroll
                for (int r2 = 0; r2 < 2; r2++) {
                    const int row = row0 + r2*8;
                    const int b_ = row >> 11, s_ = row & 2047;
                    const float2 cs1 = *(const float2*)&cosb[s_*HD + d];
                    const float2 sn1 = *(const float2*)&sinb[s_*HD + d];
                    const float2 cs2 = *(const float2*)&cosb[s_*HD + d + 32];
                    const float2 sn2 = *(const float2*)&sinb[s_*HD + d + 32];
                    const float x10 = acc[mt][nt  ][r2*2+0] + bi10;
                    const float x11 = acc[mt][nt  ][r2*2+1] + bi11;
                    const float x20 = acc[mt][nt+4][r2*2+0] + bi20;
                    const float x21 = acc[mt][nt+4][r2*2+1] + bi21;
                    const float o10 = x10*cs1.x - x20*sn1.x;
                    const float o11 = x11*cs1.y - x21*sn1.y;
                    const float o20 = x20*cs2.x + x10*sn2.x;
                    const float o21 = x21*cs2.y + x11*sn2.y;
                    const size_t base = (((size_t)b_*HH + h)*SS + s_)*HD;
                    HI[(base + d     ) >> 1] = pack_bf2(o10, o11);
                    LO[(base + d     ) >> 1] = pack_bf2(bf_res(o10), bf_res(o11));
                    HI[(base + d + 32) >> 1] = pack_bf2(o20, o21);
                    LO[(base + d + 32) >> 1] = pack_bf2(bf_res(o20), bf_res(o21));
                }
            }
        }
    } else {
        #pragma unroll
        for (int mt = 0; mt < 2; mt++) {
            const int row0 = m0 + wm + mt*16 + g;
            const int row1 = row0 + 8;
            #pragma unroll
            for (int nt = 0; nt < 8; nt++) {
                const int col = n0 + wn + nt*8 + 2*q;
                const float b0 = bias[col], b1 = bias[col + 1];
                const float v00 = acc[mt][nt][0] + b0, v01 = acc[mt][nt][1] + b1;
                const float v10 = acc[mt][nt][2] + b0, v11 = acc[mt][nt][3] + b1;
                if (mode == 1) {
                    const int h = col >> 6, d = col & 63;
                    const int b_0 = row0 >> 11, s_0 = row0 & 2047;
                    const int b_1 = row1 >> 11, s_1 = row1 & 2047;
                    *(float2*)&Cf[(((size_t)b_0*HH + h)*SS + s_0)*HD + d] = make_float2(v00, v01);
                    *(float2*)&Cf[(((size_t)b_1*HH + h)*SS + s_1)*HD + d] = make_float2(v10, v11);
                } else {
                    *(float2*)&Cf[(size_t)row0*DD + col] = make_float2(v00, v01);
                    *(float2*)&Cf[(size_t)row1*DD + col] = make_float2(v10, v11);
                }
            }
        }
    }
}

// ---------------------------------------------------------------------------
// FlashAttention-2 (causal), bf16x3, ldmatrix + register-passed P.
// 4 warps, 64 q-rows/block, KV tiles 64. Writes bf16 hi/lo out [B,S,D].
// ---------------------------------------------------------------------------
#define KST 36
#define ATTN_SMEM (4*64*KST*4)   // 36864 B

__global__ __launch_bounds__(128) void attn_bf3_kernel(
    const __nv_bfloat16* __restrict__ Qh, const __nv_bfloat16* __restrict__ Ql,
    const __nv_bfloat16* __restrict__ Kh, const __nv_bfloat16* __restrict__ Kl,
    const __nv_bfloat16* __restrict__ Vth, const __nv_bfloat16* __restrict__ Vtl,
    __nv_bfloat16* __restrict__ OutHi, __nv_bfloat16* __restrict__ OutLo)
{
    extern __shared__ uint32_t su[];
    uint32_t* KsH = su;
    uint32_t* KsL = su + 64*KST;
    uint32_t* VsH = su + 2*64*KST;
    uint32_t* VsL = su + 3*64*KST;
    const uint32_t smb  = (uint32_t)__cvta_generic_to_shared(su);
    const uint32_t aKsH = smb;
    const uint32_t aKsL = smb + 64*KST*4;
    const uint32_t aVsH = smb + 2*64*KST*4;
    const uint32_t aVsL = smb + 3*64*KST*4;

    const int tid  = threadIdx.x;
    const int w    = tid >> 5;
    const int lane = tid & 31;
    const int g    = lane >> 2;
    const int q    = lane & 3;
    const int qt   = (SS/64 - 1) - blockIdx.x;   // heavy tiles first
    const int bh   = blockIdx.y;
    const int q0   = qt * 64;
    const size_t hb = (size_t)bh * SS * HD;

    const uint32_t aoff = (uint32_t)(((((lane>>3)&1)*8 + (lane&7))*KST + ((lane>>4)*4)) * 4);
    const uint32_t boff = (uint32_t)((((lane>>4)*8 + (lane&7))*KST + (((lane>>3)&1)*4)) * 4);

    // stage Q into KsH/KsL, then preload fragments
    #pragma unroll
    for (int i = 0; i < 4; i++) {
        int c = tid + 128*i;
        int row = c >> 3, col16 = c & 7;
        size_t go = hb + (size_t)(q0 + row)*HD + col16*8;
        *(uint4*)&KsH[row*KST + col16*4] = *(const uint4*)(Qh + go);
        *(uint4*)&KsL[row*KST + col16*4] = *(const uint4*)(Ql + go);
    }
    __syncthreads();

    const int rb = 16*w;
    uint32_t rQh[4][4], rQl[4][4];
    #pragma unroll
    for (int ks = 0; ks < 4; ks++) {
        const uint32_t ro = (uint32_t)(rb*KST*4) + ks*32;
        ldsm_x4(rQh[ks], aKsH + aoff + ro);
        ldsm_x4(rQl[ks], aKsL + aoff + ro);
    }

    float oc[8][4];
    #pragma unroll
    for (int nt = 0; nt < 8; nt++)
        #pragma unroll
        for (int r = 0; r < 4; r++) oc[nt][r] = 0.f;
    float m0 = -1e30f, m1 = -1e30f, l0 = 0.f, l1 = 0.f;

    const int row0g = q0 + 16*w + g;
    const int row1g = row0g + 8;

    for (int kt = 0; kt <= qt; kt++) {
        const int k0 = kt * 64;
        __syncthreads();   // Q frag reads (1st iter) / prev K,V reads done

        #pragma unroll
        for (int i = 0; i < 4; i++) {
            int c = tid + 128*i;
            int row = c >> 3, col16 = c & 7;
            size_t ko = hb + (size_t)(k0 + row)*HD + col16*8;
            *(uint4*)&KsH[row*KST + col16*4] = *(const uint4*)(Kh + ko);
            *(uint4*)&KsL[row*KST + col16*4] = *(const uint4*)(Kl + ko);
            size_t vo = ((size_t)bh*HD + row)*SS + k0 + col16*8;
            *(uint4*)&VsH[row*KST + col16*4] = *(const uint4*)(Vth + vo);
            *(uint4*)&VsL[row*KST + col16*4] = *(const uint4*)(Vtl + vo);
        }
        __syncthreads();

        // scores
        float sc[8][4];
        #pragma unroll
        for (int nt = 0; nt < 8; nt++)
            #pragma unroll
            for (int r = 0; r < 4; r++) sc[nt][r] = 0.f;

        #pragma unroll
        for (int ks = 0; ks < 4; ks++) {
            const uint32_t kbyte = ks*32;
            #pragma unroll
            for (int ntp = 0; ntp < 4; ntp++) {
                const uint32_t ro = (uint32_t)(ntp*16*KST*4) + kbyte;
                uint32_t kh4[4], kl4[4];
                ldsm_x4(kh4, aKsH + boff + ro);
                ldsm_x4(kl4, aKsL + boff + ro);
                #pragma unroll
                for (int j = 0; j < 2; j++) {
                    const int nt = 2*ntp + j;
                    mma_bf16(sc[nt], rQh[ks], kh4[2*j], kh4[2*j+1]);
                    mma_bf16(sc[nt], rQh[ks], kl4[2*j], kl4[2*j+1]);
                    mma_bf16(sc[nt], rQl[ks], kh4[2*j], kh4[2*j+1]);
                }
            }
        }

        // scale + causal mask
        const float scale = 0.125f;
        const bool diag = (kt == qt);
        #pragma unroll
        for (int nt = 0; nt < 8; nt++) {
            const int colb = k0 + nt*8 + 2*q;
            #pragma unroll
            for (int j = 0; j < 2; j++) {
                float v0 = sc[nt][j]   * scale;
                float v1 = sc[nt][2+j] * scale;
                if (diag && (colb + j) > row0g) v0 = -1e30f;
                if (diag && (colb + j) > row1g) v1 = -1e30f;
                sc[nt][j]   = v0;
                sc[nt][2+j] = v1;
            }
        }

        // online softmax
        float mx0 = -1e30f, mx1 = -1e30f;
        #pragma unroll
        for (int nt = 0; nt < 8; nt++) {
            mx0 = fmaxf(mx0, fmaxf(sc[nt][0], sc[nt][1]));
            mx1 = fmaxf(mx1, fmaxf(sc[nt][2], sc[nt][3]));
        }
        mx0 = fmaxf(mx0, __shfl_xor_sync(0xffffffffu, mx0, 1));
        mx0 = fmaxf(mx0, __shfl_xor_sync(0xffffffffu, mx0, 2));
        mx1 = fmaxf(mx1, __shfl_xor_sync(0xffffffffu, mx1, 1));
        mx1 = fmaxf(mx1, __shfl_xor_sync(0xffffffffu, mx1, 2));
        const float mn0 = fmaxf(m0, mx0);
        const float mn1 = fmaxf(m1, mx1);
        const float a0 = __expf(m0 - mn0);
        const float a1 = __expf(m1 - mn1);
        m0 = mn0; m1 = mn1;

        uint32_t ph[8][2], pl[8][2];
        float s0 = 0.f, s1 = 0.f;
        #pragma unroll
        for (int nt = 0; nt < 8; nt++) {
            float p00 = __expf(sc[nt][0] - mn0);
            float p01 = __expf(sc[nt][1] - mn0);
            float p10 = __expf(sc[nt][2] - mn1);
            float p11 = __expf(sc[nt][3] - mn1);
            s0 += p00 + p01;
            s1 += p10 + p11;
            ph[nt][0] = pack_bf2(p00, p01);
            ph[nt][1] = pack_bf2(p10, p11);
            pl[nt][0] = pack_bf2(bf_res(p00), bf_res(p01));
            pl[nt][1] = pack_bf2(bf_res(p10), bf_res(p11));
        }
        s0 += __shfl_xor_sync(0xffffffffu, s0, 1);
        s0 += __shfl_xor_sync(0xffffffffu, s0, 2);
        s1 += __shfl_xor_sync(0xffffffffu, s1, 1);
        s1 += __shfl_xor_sync(0xffffffffu, s1, 2);
        l0 = l0*a0 + s0;
        l1 = l1*a1 + s1;
        #pragma unroll
        for (int nt = 0; nt < 8; nt++) {
            oc[nt][0] *= a0; oc[nt][1] *= a0;
            oc[nt][2] *= a1; oc[nt][3] *= a1;
        }

        // PV: P passed in registers (score C-frag == PV A-frag layout)
        #pragma unroll
        for (int kc = 0; kc < 4; kc++) {
            uint32_t ah4[4] = { ph[2*kc][0], ph[2*kc][1], ph[2*kc+1][0], ph[2*kc+1][1] };
            uint32_t al4[4] = { pl[2*kc][0], pl[2*kc][1], pl[2*kc+1][0], pl[2*kc+1][1] };
            const uint32_t kbyte = kc*32;
            #pragma unroll
            for (int ntp = 0; ntp < 4; ntp++) {
                const uint32_t ro = (uint32_t)(ntp*16*KST*4) + kbyte;
                uint32_t vh4[4], vl4[4];
                ldsm_x4(vh4, aVsH + boff + ro);
                ldsm_x4(vl4, aVsL + boff + ro);
                #pragma unroll
                for (int j = 0; j < 2; j++) {
                    const int nto = 2*ntp + j;
                    mma_bf16(oc[nto], ah4, vh4[2*j], vh4[2*j+1]);
                    mma_bf16(oc[nto], ah4, vl4[2*j], vl4[2*j+1]);
                    mma_bf16(oc[nto], al4, vh4[2*j], vh4[2*j+1]);
                }
            }
        }
    }

    // epilogue: normalize + split + write bf16 hi/lo [B,S,D]
    const float i0 = 1.f / l0;
    const float i1 = 1.f / l1;
    const int b = bh >> 4;
    const int h = bh & 15;
    const size_t o0 = ((size_t)(b*SS + row0g))*DD + h*HD;
    const size_t o1 = ((size_t)(b*SS + row1g))*DD + h*HD;
    uint32_t* HI = (uint32_t*)OutHi;
    uint32_t* LO = (uint32_t*)OutLo;
    #pragma unroll
    for (int nt = 0; nt < 8; nt++) {
        const int col = nt*8 + 2*q;
        const float v00 = oc[nt][0]*i0, v01 = oc[nt][1]*i0;
        const float v10 = oc[nt][2]*i1, v11 = oc[nt][3]*i1;
        HI[(o0 + col) >> 1] = pack_bf2(v00, v01);
        LO[(o0 + col) >> 1] = pack_bf2(bf_res(v00), bf_res(v01));
        HI[(o1 + col) >> 1] = pack_bf2(v10, v11);
        LO[(o1 + col) >> 1] = pack_bf2(bf_res(v10), bf_res(v11));
    }
}

// ---------------------------------------------------------------------------
// Launch
// ---------------------------------------------------------------------------
extern "C" void kernel_launch(void* const* d_in, const int* in_sizes, int n_in,
                              void* d_out, int out_size)
{
    const float* x    = (const float*)d_in[0];
    const float* cosb = (const float*)d_in[1];
    const float* sinb = (const float*)d_in[2];
    const float* Wq = (const float*)d_in[4];
    const float* bq = (const float*)d_in[5];
    const float* Wk = (const float*)d_in[6];
    const float* bk = (const float*)d_in[7];
    const float* Wv = (const float*)d_in[8];
    const float* bv = (const float*)d_in[9];
    const float* Wo = (const float*)d_in[10];
    const float* bo = (const float*)d_in[11];
    float* out = (float*)d_out;

    float *vp;
    __nv_bfloat16 *xhi, *xlo, *ahi, *alo, *qhi, *qlo, *khi, *klo, *vthi, *vtlo;
    __nv_bfloat16 *wh, *wl;
    cudaGetSymbolAddress((void**)&vp,   g_v);
    cudaGetSymbolAddress((void**)&xhi,  g_xhi);
    cudaGetSymbolAddress((void**)&xlo,  g_xlo);
    cudaGetSymbolAddress((void**)&ahi,  g_ahi);
    cudaGetSymbolAddress((void**)&alo,  g_alo);
    cudaGetSymbolAddress((void**)&qhi,  g_qhi);
    cudaGetSymbolAddress((void**)&qlo,  g_qlo);
    cudaGetSymbolAddress((void**)&khi,  g_khi);
    cudaGetSymbolAddress((void**)&klo,  g_klo);
    cudaGetSymbolAddress((void**)&vthi, g_vthi);
    cudaGetSymbolAddress((void**)&vtlo, g_vtlo);
    cudaGetSymbolAddress((void**)&wh,   g_wh);
    cudaGetSymbolAddress((void**)&wl,   g_wl);

    cudaFuncSetAttribute(gemm_bf3_kernel,
                         cudaFuncAttributeMaxDynamicSharedMemorySize, GEMM_SMEM);
    cudaFuncSetAttribute(attn_bf3_kernel,
                         cudaFuncAttributeMaxDynamicSharedMemorySize, ATTN_SMEM);

    // splits
    split4_kernel<<<NX/4/256, 256>>>(x, xhi, xlo, NX/4);
    split4_kernel<<<NW/4/256, 256>>>(Wq, wh + 0*(size_t)NW, wl + 0*(size_t)NW, NW/4);
    split4_kernel<<<NW/4/256, 256>>>(Wk, wh + 1*(size_t)NW, wl + 1*(size_t)NW, NW/4);
    split4_kernel<<<NW/4/256, 256>>>(Wv, wh + 2*(size_t)NW, wl + 2*(size_t)NW, NW/4);
    split4_kernel<<<NW/4/256, 256>>>(Wo, wh + 3*(size_t)NW, wl + 3*(size_t)NW, NW/4);

    dim3 ggrid(DD/128, BS/128);   // (8, 64)
    // Q, K: rope fused, bf16 hi/lo out
    gemm_bf3_kernel<<<ggrid, 256, GEMM_SMEM>>>(xhi, xlo, wh + 0*(size_t)NW, wl + 0*(size_t)NW,
                                               bq, cosb, sinb, nullptr, qhi, qlo, 2);
    gemm_bf3_kernel<<<ggrid, 256, GEMM_SMEM>>>(xhi, xlo, wh + 1*(size_t)NW, wl + 1*(size_t)NW,
                                               bk, cosb, sinb, nullptr, khi, klo, 2);
    // V: head-major fp32, then transpose+split
    gemm_bf3_kernel<<<ggrid, 256, GEMM_SMEM>>>(xhi, xlo, wh + 2*(size_t)NW, wl + 2*(size_t)NW,
                                               bv, nullptr, nullptr, vp, nullptr, nullptr, 1);
    vtrans_split_kernel<<<dim3(SS/64, BB*HH), 256>>>(vp, vthi, vtlo);

    // attention -> bf16 hi/lo directly
    attn_bf3_kernel<<<dim3(SS/64, BB*HH), 128, ATTN_SMEM>>>(
        qhi, qlo, khi, klo, vthi, vtlo, ahi, alo);

    // output projection (plain fp32 out)
    gemm_bf3_kernel<<<ggrid, 256, GEMM_SMEM>>>(ahi, alo, wh + 3*(size_t)NW, wl + 3*(size_t)NW,
                                               bo, nullptr, nullptr, out, nullptr, nullptr, 0);
}

// round 7
// speedup vs baseline: 5.2619x; 1.0247x over previous
#include <cuda_runtime.h>
#include <cuda_bf16.h>
#include <stdint.h>

// Problem constants
#define BB 4
#define SS 2048
#define DD 1024
#define HH 16
#define HD 64
#define BS (BB*SS)
#define NQ (BB*HH*SS*HD)
#define NX (BS*DD)
#define NW (DD*DD)

// ---------------------------------------------------------------------------
// Static device scratch
// ---------------------------------------------------------------------------
__device__ float g_v[NQ];                             // V fp32 head-major
__device__ __nv_bfloat16 g_xhi[NX],  g_xlo[NX];
__device__ __nv_bfloat16 g_ahi[NX],  g_alo[NX];       // attention out hi/lo
__device__ __nv_bfloat16 g_qhi[NQ],  g_qlo[NQ];
__device__ __nv_bfloat16 g_khi[NQ],  g_klo[NQ];
__device__ __nv_bfloat16 g_vthi[NQ], g_vtlo[NQ];      // [B,H,HD,S]
__device__ __nv_bfloat16 g_wh[4][NW], g_wl[4][NW];

// ---------------------------------------------------------------------------
// helpers
// ---------------------------------------------------------------------------
__device__ __forceinline__ uint32_t pack_bf2(float a, float b) {
    __nv_bfloat16 ha = __float2bfloat16(a), hb = __float2bfloat16(b);
    unsigned short ua = *reinterpret_cast<unsigned short*>(&ha);
    unsigned short ub = *reinterpret_cast<unsigned short*>(&hb);
    return (uint32_t)ua | ((uint32_t)ub << 16);
}
__device__ __forceinline__ float bf_res(float x) {
    __nv_bfloat16 h = __float2bfloat16(x);
    return x - __bfloat162float(h);
}

__device__ __forceinline__ void mma_bf16(float* c, const uint32_t* a,
                                         uint32_t b0, uint32_t b1)
{
    asm("mma.sync.aligned.m16n8k16.row.col.f32.bf16.bf16.f32 "
        "{%0,%1,%2,%3},{%4,%5,%6,%7},{%8,%9},{%0,%1,%2,%3};"
        : "+f"(c[0]), "+f"(c[1]), "+f"(c[2]), "+f"(c[3])
        : "r"(a[0]), "r"(a[1]), "r"(a[2]), "r"(a[3]), "r"(b0), "r"(b1));
}

__device__ __forceinline__ void ldsm_x4(uint32_t* r, uint32_t addr) {
    asm volatile("ldmatrix.sync.aligned.m8n8.x4.shared.b16 {%0,%1,%2,%3}, [%4];"
        : "=r"(r[0]), "=r"(r[1]), "=r"(r[2]), "=r"(r[3]) : "r"(addr));
}

#define CP16(dst_smem_u32, src_gptr) \
    asm volatile("cp.async.cg.shared.global [%0], [%1], 16;\n" \
                 :: "r"(dst_smem_u32), "l"(src_gptr))
#define CP_COMMIT() asm volatile("cp.async.commit_group;\n")
#define CP_WAIT1()  asm volatile("cp.async.wait_group 1;\n")
#define CP_WAIT0()  asm volatile("cp.async.wait_group 0;\n")

// ---------------------------------------------------------------------------
// split fp32 -> bf16 hi/lo
// ---------------------------------------------------------------------------
__global__ __launch_bounds__(256) void split4_kernel(
    const float* __restrict__ in, __nv_bfloat16* __restrict__ hi,
    __nv_bfloat16* __restrict__ lo, int n4)
{
    int i = blockIdx.x * blockDim.x + threadIdx.x;
    if (i >= n4) return;
    float4 v = ((const float4*)in)[i];
    ((uint2*)hi)[i] = make_uint2(pack_bf2(v.x, v.y), pack_bf2(v.z, v.w));
    ((uint2*)lo)[i] = make_uint2(pack_bf2(bf_res(v.x), bf_res(v.y)),
                                 pack_bf2(bf_res(v.z), bf_res(v.w)));
}

// ---------------------------------------------------------------------------
// V transpose + split: [B,H,S,HD] fp32 -> [B,H,HD,S] bf16 hi/lo
// ---------------------------------------------------------------------------
__global__ __launch_bounds__(256) void vtrans_split_kernel(
    const float* __restrict__ v,
    __nv_bfloat16* __restrict__ thi, __nv_bfloat16* __restrict__ tlo)
{
    __shared__ float tile[64][65];
    const int tid = threadIdx.x;
    const int s0  = blockIdx.x * 64;
    const int bh  = blockIdx.y;
    const size_t base_in  = ((size_t)bh * SS + s0) * HD;
    const size_t base_out = (size_t)bh * HD * SS;

    #pragma unroll
    for (int i = 0; i < 16; i++) {
        int c = tid + 256*i;
        int srow = c >> 6, d = c & 63;
        tile[srow][d] = v[base_in + (size_t)srow*HD + d];
    }
    __syncthreads();
    #pragma unroll
    for (int i = 0; i < 16; i++) {
        int c = tid + 256*i;
        int drow = c >> 6, scol = c & 63;
        float val = tile[scol][drow];
        thi[base_out + (size_t)drow*SS + s0 + scol] = __float2bfloat16(val);
        tlo[base_out + (size_t)drow*SS + s0 + scol] = __float2bfloat16(bf_res(val));
    }
}

// ---------------------------------------------------------------------------
// GEMM (bf16x3, ldmatrix): C = A.W^T + bias   (unchanged from round 6)
// mode 0: plain fp32 out; mode 1: head-major fp32; mode 2: rope+split bf16
// ---------------------------------------------------------------------------
#define RST 20
#define OPB (128*RST)
#define GEMM_SMEM (8*OPB*4)

__global__ __launch_bounds__(256, 2) void gemm_bf3_kernel(
    const __nv_bfloat16* __restrict__ Ah, const __nv_bfloat16* __restrict__ Al,
    const __nv_bfloat16* __restrict__ Wh, const __nv_bfloat16* __restrict__ Wl,
    const float* __restrict__ bias, const float* __restrict__ cosb,
    const float* __restrict__ sinb, float* __restrict__ Cf,
    __nv_bfloat16* __restrict__ Chi, __nv_bfloat16* __restrict__ Clo, int mode)
{
    extern __shared__ uint32_t su[];
    const uint32_t smb = (uint32_t)__cvta_generic_to_shared(su);

    const int tid  = threadIdx.x;
    const int m0   = blockIdx.y * 128;
    const int n0   = blockIdx.x * 128;
    const int w    = tid >> 5;
    const int lane = tid & 31;
    const int g    = lane >> 2;
    const int q    = lane & 3;
    const int wm   = (w & 3) * 32;
    const int wn   = (w >> 2) * 64;

    const uint32_t aoff = (uint32_t)(((((lane>>3)&1)*8 + (lane&7))*RST + ((lane>>4)*4)) * 4);
    const uint32_t boff = (uint32_t)((((lane>>4)*8 + (lane&7))*RST + (((lane>>3)&1)*4)) * 4);

    float acc[2][8][4];
    #pragma unroll
    for (int mt = 0; mt < 2; mt++)
        #pragma unroll
        for (int nt = 0; nt < 8; nt++)
            #pragma unroll
            for (int r = 0; r < 4; r++) acc[mt][nt][r] = 0.f;

    const int NK = DD / 32;

    #define LOAD_STAGE(kt, stg) do {                                          \
        uint32_t sb_ = smb + (stg)*4*OPB*4;                                   \
        _Pragma("unroll")                                                     \
        for (int i_ = 0; i_ < 2; i_++) {                                      \
            int c_ = tid + 256*i_;                                            \
            int row_ = c_ >> 2, col16_ = c_ & 3;                              \
            uint32_t so_ = sb_ + (uint32_t)((row_*RST + col16_*4)*4);         \
            size_t ga_ = (size_t)(m0+row_)*DD + (kt)*32 + col16_*8;           \
            size_t gw_ = (size_t)(n0+row_)*DD + (kt)*32 + col16_*8;           \
            CP16(so_,           Ah + ga_);                                    \
            CP16(so_ + OPB*4,   Al + ga_);                                    \
            CP16(so_ + 2*OPB*4, Wh + gw_);                                    \
            CP16(so_ + 3*OPB*4, Wl + gw_);                                    \
        }                                                                     \
        CP_COMMIT();                                                          \
    } while (0)

    LOAD_STAGE(0, 0);

    for (int it = 0; it < NK; it++) {
        if (it + 1 < NK) {
            LOAD_STAGE(it + 1, (it + 1) & 1);
            CP_WAIT1();
        } else {
            CP_WAIT0();
        }
        __syncthreads();

        const uint32_t sb  = smb + (it & 1)*4*OPB*4;
        const uint32_t ahB = sb;
        const uint32_t alB = sb + OPB*4;
        const uint32_t whB = sb + 2*OPB*4;
        const uint32_t wlB = sb + 3*OPB*4;

        #pragma unroll
        for (int s16 = 0; s16 < 2; s16++) {
            const uint32_t kbyte = s16 * 32;
            uint32_t ah[2][4], al[2][4];
            #pragma unroll
            for (int mt = 0; mt < 2; mt++) {
                const uint32_t ro = (uint32_t)((wm + mt*16)*RST*4);
                ldsm_x4(ah[mt], ahB + aoff + ro + kbyte);
                ldsm_x4(al[mt], alB + aoff + ro + kbyte);
            }
            #pragma unroll
            for (int ntp = 0; ntp < 4; ntp++) {
                const uint32_t ro = (uint32_t)((wn + ntp*16)*RST*4);
                uint32_t wh4[4], wl4[4];
                ldsm_x4(wh4, whB + boff + ro + kbyte);
                ldsm_x4(wl4, wlB + boff + ro + kbyte);
                #pragma unroll
                for (int j = 0; j < 2; j++) {
                    const int nt = 2*ntp + j;
                    const uint32_t bh0 = wh4[2*j], bh1 = wh4[2*j+1];
                    const uint32_t bl0 = wl4[2*j], bl1 = wl4[2*j+1];
                    #pragma unroll
                    for (int mt = 0; mt < 2; mt++) {
                        mma_bf16(acc[mt][nt], ah[mt], bh0, bh1);
                        mma_bf16(acc[mt][nt], ah[mt], bl0, bl1);
                        mma_bf16(acc[mt][nt], al[mt], bh0, bh1);
                    }
                }
            }
        }
        __syncthreads();
    }
    #undef LOAD_STAGE

    if (mode == 2) {
        uint32_t* HI = (uint32_t*)Chi;
        uint32_t* LO = (uint32_t*)Clo;
        #pragma unroll
        for (int mt = 0; mt < 2; mt++) {
            const int row0 = m0 + wm + mt*16 + g;
            #pragma unroll
            for (int nt = 0; nt < 4; nt++) {
                const int col = n0 + wn + nt*8 + 2*q;
                const int d = col & 63, h = col >> 6;
                const float bi10 = bias[col],    bi11 = bias[col+1];
                const float bi20 = bias[col+32], bi21 = bias[col+33];
                #pragma unroll
                for (int r2 = 0; r2 < 2; r2++) {
                    const int row = row0 + r2*8;
                    const int b_ = row >> 11, s_ = row & 2047;
                    const float2 cs1 = *(const float2*)&cosb[s_*HD + d];
                    const float2 sn1 = *(const float2*)&sinb[s_*HD + d];
                    const float2 cs2 = *(const float2*)&cosb[s_*HD + d + 32];
                    const float2 sn2 = *(const float2*)&sinb[s_*HD + d + 32];
                    const float x10 = acc[mt][nt  ][r2*2+0] + bi10;
                    const float x11 = acc[mt][nt  ][r2*2+1] + bi11;
                    const float x20 = acc[mt][nt+4][r2*2+0] + bi20;
                    const float x21 = acc[mt][nt+4][r2*2+1] + bi21;
                    const float o10 = x10*cs1.x - x20*sn1.x;
                    const float o11 = x11*cs1.y - x21*sn1.y;
                    const float o20 = x20*cs2.x + x10*sn2.x;
                    const float o21 = x21*cs2.y + x11*sn2.y;
                    const size_t base = (((size_t)b_*HH + h)*SS + s_)*HD;
                    HI[(base + d     ) >> 1] = pack_bf2(o10, o11);
                    LO[(base + d     ) >> 1] = pack_bf2(bf_res(o10), bf_res(o11));
                    HI[(base + d + 32) >> 1] = pack_bf2(o20, o21);
                    LO[(base + d + 32) >> 1] = pack_bf2(bf_res(o20), bf_res(o21));
                }
            }
        }
    } else {
        #pragma unroll
        for (int mt = 0; mt < 2; mt++) {
            const int row0 = m0 + wm + mt*16 + g;
            const int row1 = row0 + 8;
            #pragma unroll
            for (int nt = 0; nt < 8; nt++) {
                const int col = n0 + wn + nt*8 + 2*q;
                const float b0 = bias[col], b1 = bias[col + 1];
                const float v00 = acc[mt][nt][0] + b0, v01 = acc[mt][nt][1] + b1;
                const float v10 = acc[mt][nt][2] + b0, v11 = acc[mt][nt][3] + b1;
                if (mode == 1) {
                    const int h = col >> 6, d = col & 63;
                    const int b_0 = row0 >> 11, s_0 = row0 & 2047;
                    const int b_1 = row1 >> 11, s_1 = row1 & 2047;
                    *(float2*)&Cf[(((size_t)b_0*HH + h)*SS + s_0)*HD + d] = make_float2(v00, v01);
                    *(float2*)&Cf[(((size_t)b_1*HH + h)*SS + s_1)*HD + d] = make_float2(v10, v11);
                } else {
                    *(float2*)&Cf[(size_t)row0*DD + col] = make_float2(v00, v01);
                    *(float2*)&Cf[(size_t)row1*DD + col] = make_float2(v10, v11);
                }
            }
        }
    }
}

// ---------------------------------------------------------------------------
// FlashAttention-2 (causal), bf16x3, ldmatrix + register-P + cp.async
// double-buffered KV tiles. 4 warps, 64 q-rows/block, KV tiles 64.
// ---------------------------------------------------------------------------
#define KST 36
#define ATILE (64*KST)               // u32 per buffer (9216 B)
#define ASTG  (4*ATILE)              // u32 per stage {Kh,Kl,Vh,Vl}
#define ATTN_SMEM (2*ASTG*4)         // 73728 B

__device__ __forceinline__ void attn_prefetch(
    uint32_t sstage,
    const __nv_bfloat16* __restrict__ Kh, const __nv_bfloat16* __restrict__ Kl,
    const __nv_bfloat16* __restrict__ Vth, const __nv_bfloat16* __restrict__ Vtl,
    size_t hb, int bh, int k0, int tid)
{
    #pragma unroll
    for (int i = 0; i < 4; i++) {
        int c = tid + 128*i;               // 512 chunks per buffer
        int row = c >> 3, c16 = c & 7;
        uint32_t so = sstage + (uint32_t)((row*KST + c16*4)*4);
        size_t ko = hb + (size_t)(k0 + row)*HD + c16*8;
        CP16(so,             Kh + ko);
        CP16(so + ATILE*4,   Kl + ko);
        size_t vo = ((size_t)bh*HD + row)*SS + k0 + c16*8;
        CP16(so + 2*ATILE*4, Vth + vo);
        CP16(so + 3*ATILE*4, Vtl + vo);
    }
    CP_COMMIT();
}

__global__ __launch_bounds__(128) void attn_bf3_kernel(
    const __nv_bfloat16* __restrict__ Qh, const __nv_bfloat16* __restrict__ Ql,
    const __nv_bfloat16* __restrict__ Kh, const __nv_bfloat16* __restrict__ Kl,
    const __nv_bfloat16* __restrict__ Vth, const __nv_bfloat16* __restrict__ Vtl,
    __nv_bfloat16* __restrict__ OutHi, __nv_bfloat16* __restrict__ OutLo)
{
    extern __shared__ uint32_t su[];
    const uint32_t smb = (uint32_t)__cvta_generic_to_shared(su);

    const int tid  = threadIdx.x;
    const int w    = tid >> 5;
    const int lane = tid & 31;
    const int g    = lane >> 2;
    const int q    = lane & 3;
    const int qt   = (SS/64 - 1) - blockIdx.x;   // heavy tiles first
    const int bh   = blockIdx.y;
    const int q0   = qt * 64;
    const size_t hb = (size_t)bh * SS * HD;

    const uint32_t aoff = (uint32_t)(((((lane>>3)&1)*8 + (lane&7))*KST + ((lane>>4)*4)) * 4);
    const uint32_t boff = (uint32_t)((((lane>>4)*8 + (lane&7))*KST + (((lane>>3)&1)*4)) * 4);

    // stage Q into stage1's K buffers (cp.async), overlapped with stage0 KV prefetch
    #pragma unroll
    for (int i = 0; i < 4; i++) {
        int c = tid + 128*i;
        int row = c >> 3, c16 = c & 7;
        uint32_t so = smb + ASTG*4 + (uint32_t)((row*KST + c16*4)*4);
        size_t go = hb + (size_t)(q0 + row)*HD + c16*8;
        CP16(so,           Qh + go);
        CP16(so + ATILE*4, Ql + go);
    }
    CP_COMMIT();
    attn_prefetch(smb, Kh, Kl, Vth, Vtl, hb, bh, 0, tid);     // stage0 <- kt 0

    CP_WAIT1();            // Q staged (stage0 prefetch may still be in flight)
    __syncthreads();

    const int rb = 16*w;
    uint32_t rQh[4][4], rQl[4][4];
    #pragma unroll
    for (int ks = 0; ks < 4; ks++) {
        const uint32_t ro = (uint32_t)(rb*KST*4) + ks*32;
        ldsm_x4(rQh[ks], smb + ASTG*4 + aoff + ro);
        ldsm_x4(rQl[ks], smb + ASTG*4 + ATILE*4 + aoff + ro);
    }
    __syncthreads();       // Q frags read before stage1 refill
    if (qt > 0)
        attn_prefetch(smb + ASTG*4, Kh, Kl, Vth, Vtl, hb, bh, 64, tid);  // stage1 <- kt 1

    float oc[8][4];
    #pragma unroll
    for (int nt = 0; nt < 8; nt++)
        #pragma unroll
        for (int r = 0; r < 4; r++) oc[nt][r] = 0.f;
    float m0 = -1e30f, m1 = -1e30f, l0 = 0.f, l1 = 0.f;

    const int row0g = q0 + 16*w + g;
    const int row1g = row0g + 8;

    for (int kt = 0; kt <= qt; kt++) {
        const int k0 = kt * 64;
        const uint32_t ab   = smb + (kt & 1)*ASTG*4;
        const uint32_t aKsH = ab;
        const uint32_t aKsL = ab + ATILE*4;
        const uint32_t aVsH = ab + 2*ATILE*4;
        const uint32_t aVsL = ab + 3*ATILE*4;

        if (kt < qt) { CP_WAIT1(); } else { CP_WAIT0(); }
        __syncthreads();

        // scores
        float sc[8][4];
        #pragma unroll
        for (int nt = 0; nt < 8; nt++)
            #pragma unroll
            for (int r = 0; r < 4; r++) sc[nt][r] = 0.f;

        #pragma unroll
        for (int ks = 0; ks < 4; ks++) {
            const uint32_t kbyte = ks*32;
            #pragma unroll
            for (int ntp = 0; ntp < 4; ntp++) {
                const uint32_t ro = (uint32_t)(ntp*16*KST*4) + kbyte;
                uint32_t kh4[4], kl4[4];
                ldsm_x4(kh4, aKsH + boff + ro);
                ldsm_x4(kl4, aKsL + boff + ro);
                #pragma unroll
                for (int j = 0; j < 2; j++) {
                    const int nt = 2*ntp + j;
                    mma_bf16(sc[nt], rQh[ks], kh4[2*j], kh4[2*j+1]);
                    mma_bf16(sc[nt], rQh[ks], kl4[2*j], kl4[2*j+1]);
                    mma_bf16(sc[nt], rQl[ks], kh4[2*j], kh4[2*j+1]);
                }
            }
        }

        // scale + causal mask
        const float scale = 0.125f;
        const bool diag = (kt == qt);
        #pragma unroll
        for (int nt = 0; nt < 8; nt++) {
            const int colb = k0 + nt*8 + 2*q;
            #pragma unroll
            for (int j = 0; j < 2; j++) {
                float v0 = sc[nt][j]   * scale;
                float v1 = sc[nt][2+j] * scale;
                if (diag && (colb + j) > row0g) v0 = -1e30f;
                if (diag && (colb + j) > row1g) v1 = -1e30f;
                sc[nt][j]   = v0;
                sc[nt][2+j] = v1;
            }
        }

        // online softmax
        float mx0 = -1e30f, mx1 = -1e30f;
        #pragma unroll
        for (int nt = 0; nt < 8; nt++) {
            mx0 = fmaxf(mx0, fmaxf(sc[nt][0], sc[nt][1]));
            mx1 = fmaxf(mx1, fmaxf(sc[nt][2], sc[nt][3]));
        }
        mx0 = fmaxf(mx0, __shfl_xor_sync(0xffffffffu, mx0, 1));
        mx0 = fmaxf(mx0, __shfl_xor_sync(0xffffffffu, mx0, 2));
        mx1 = fmaxf(mx1, __shfl_xor_sync(0xffffffffu, mx1, 1));
        mx1 = fmaxf(mx1, __shfl_xor_sync(0xffffffffu, mx1, 2));
        const float mn0 = fmaxf(m0, mx0);
        const float mn1 = fmaxf(m1, mx1);
        const float a0 = __expf(m0 - mn0);
        const float a1 = __expf(m1 - mn1);
        m0 = mn0; m1 = mn1;

        uint32_t ph[8][2], pl[8][2];
        float s0 = 0.f, s1 = 0.f;
        #pragma unroll
        for (int nt = 0; nt < 8; nt++) {
            float p00 = __expf(sc[nt][0] - mn0);
            float p01 = __expf(sc[nt][1] - mn0);
            float p10 = __expf(sc[nt][2] - mn1);
            float p11 = __expf(sc[nt][3] - mn1);
            s0 += p00 + p01;
            s1 += p10 + p11;
            ph[nt][0] = pack_bf2(p00, p01);
            ph[nt][1] = pack_bf2(p10, p11);
            pl[nt][0] = pack_bf2(bf_res(p00), bf_res(p01));
            pl[nt][1] = pack_bf2(bf_res(p10), bf_res(p11));
        }
        s0 += __shfl_xor_sync(0xffffffffu, s0, 1);
        s0 += __shfl_xor_sync(0xffffffffu, s0, 2);
        s1 += __shfl_xor_sync(0xffffffffu, s1, 1);
        s1 += __shfl_xor_sync(0xffffffffu, s1, 2);
        l0 = l0*a0 + s0;
        l1 = l1*a1 + s1;
        #pragma unroll
        for (int nt = 0; nt < 8; nt++) {
            oc[nt][0] *= a0; oc[nt][1] *= a0;
            oc[nt][2] *= a1; oc[nt][3] *= a1;
        }

        // PV: P passed in registers
        #pragma unroll
        for (int kc = 0; kc < 4; kc++) {
            uint32_t ah4[4] = { ph[2*kc][0], ph[2*kc][1], ph[2*kc+1][0], ph[2*kc+1][1] };
            uint32_t al4[4] = { pl[2*kc][0], pl[2*kc][1], pl[2*kc+1][0], pl[2*kc+1][1] };
            const uint32_t kbyte = kc*32;
            #pragma unroll
            for (int ntp = 0; ntp < 4; ntp++) {
                const uint32_t ro = (uint32_t)(ntp*16*KST*4) + kbyte;
                uint32_t vh4[4], vl4[4];
                ldsm_x4(vh4, aVsH + boff + ro);
                ldsm_x4(vl4, aVsL + boff + ro);
                #pragma unroll
                for (int j = 0; j < 2; j++) {
                    const int nto = 2*ntp + j;
                    mma_bf16(oc[nto], ah4, vh4[2*j], vh4[2*j+1]);
                    mma_bf16(oc[nto], ah4, vl4[2*j], vl4[2*j+1]);
                    mma_bf16(oc[nto], al4, vh4[2*j], vh4[2*j+1]);
                }
            }
        }

        __syncthreads();   // all warps done reading this stage
        if (kt + 2 <= qt)
            attn_prefetch(ab, Kh, Kl, Vth, Vtl, hb, bh, (kt + 2)*64, tid);
    }

    // epilogue: normalize + split + write bf16 hi/lo [B,S,D]
    const float i0 = 1.f / l0;
    const float i1 = 1.f / l1;
    const int b = bh >> 4;
    const int h = bh & 15;
    const size_t o0 = ((size_t)(b*SS + row0g))*DD + h*HD;
    const size_t o1 = ((size_t)(b*SS + row1g))*DD + h*HD;
    uint32_t* HI = (uint32_t*)OutHi;
    uint32_t* LO = (uint32_t*)OutLo;
    #pragma unroll
    for (int nt = 0; nt < 8; nt++) {
        const int col = nt*8 + 2*q;
        const float v00 = oc[nt][0]*i0, v01 = oc[nt][1]*i0;
        const float v10 = oc[nt][2]*i1, v11 = oc[nt][3]*i1;
        HI[(o0 + col) >> 1] = pack_bf2(v00, v01);
        LO[(o0 + col) >> 1] = pack_bf2(bf_res(v00), bf_res(v01));
        HI[(o1 + col) >> 1] = pack_bf2(v10, v11);
        LO[(o1 + col) >> 1] = pack_bf2(bf_res(v10), bf_res(v11));
    }
}

// ---------------------------------------------------------------------------
// Launch
// ---------------------------------------------------------------------------
extern "C" void kernel_launch(void* const* d_in, const int* in_sizes, int n_in,
                              void* d_out, int out_size)
{
    const float* x    = (const float*)d_in[0];
    const float* cosb = (const float*)d_in[1];
    const float* sinb = (const float*)d_in[2];
    const float* Wq = (const float*)d_in[4];
    const float* bq = (const float*)d_in[5];
    const float* Wk = (const float*)d_in[6];
    const float* bk = (const float*)d_in[7];
    const float* Wv = (const float*)d_in[8];
    const float* bv = (const float*)d_in[9];
    const float* Wo = (const float*)d_in[10];
    const float* bo = (const float*)d_in[11];
    float* out = (float*)d_out;

    float *vp;
    __nv_bfloat16 *xhi, *xlo, *ahi, *alo, *qhi, *qlo, *khi, *klo, *vthi, *vtlo;
    __nv_bfloat16 *wh, *wl;
    cudaGetSymbolAddress((void**)&vp,   g_v);
    cudaGetSymbolAddress((void**)&xhi,  g_xhi);
    cudaGetSymbolAddress((void**)&xlo,  g_xlo);
    cudaGetSymbolAddress((void**)&ahi,  g_ahi);
    cudaGetSymbolAddress((void**)&alo,  g_alo);
    cudaGetSymbolAddress((void**)&qhi,  g_qhi);
    cudaGetSymbolAddress((void**)&qlo,  g_qlo);
    cudaGetSymbolAddress((void**)&khi,  g_khi);
    cudaGetSymbolAddress((void**)&klo,  g_klo);
    cudaGetSymbolAddress((void**)&vthi, g_vthi);
    cudaGetSymbolAddress((void**)&vtlo, g_vtlo);
    cudaGetSymbolAddress((void**)&wh,   g_wh);
    cudaGetSymbolAddress((void**)&wl,   g_wl);

    cudaFuncSetAttribute(gemm_bf3_kernel,
                         cudaFuncAttributeMaxDynamicSharedMemorySize, GEMM_SMEM);
    cudaFuncSetAttribute(attn_bf3_kernel,
                         cudaFuncAttributeMaxDynamicSharedMemorySize, ATTN_SMEM);

    // splits
    split4_kernel<<<NX/4/256, 256>>>(x, xhi, xlo, NX/4);
    split4_kernel<<<NW/4/256, 256>>>(Wq, wh + 0*(size_t)NW, wl + 0*(size_t)NW, NW/4);
    split4_kernel<<<NW/4/256, 256>>>(Wk, wh + 1*(size_t)NW, wl + 1*(size_t)NW, NW/4);
    split4_kernel<<<NW/4/256, 256>>>(Wv, wh + 2*(size_t)NW, wl + 2*(size_t)NW, NW/4);
    split4_kernel<<<NW/4/256, 256>>>(Wo, wh + 3*(size_t)NW, wl + 3*(size_t)NW, NW/4);

    dim3 ggrid(DD/128, BS/128);   // (8, 64)
    gemm_bf3_kernel<<<ggrid, 256, GEMM_SMEM>>>(xhi, xlo, wh + 0*(size_t)NW, wl + 0*(size_t)NW,
                                               bq, cosb, sinb, nullptr, qhi, qlo, 2);
    gemm_bf3_kernel<<<ggrid, 256, GEMM_SMEM>>>(xhi, xlo, wh + 1*(size_t)NW, wl + 1*(size_t)NW,
                                               bk, cosb, sinb, nullptr, khi, klo, 2);
    gemm_bf3_kernel<<<ggrid, 256, GEMM_SMEM>>>(xhi, xlo, wh + 2*(size_t)NW, wl + 2*(size_t)NW,
                                               bv, nullptr, nullptr, vp, nullptr, nullptr, 1);
    vtrans_split_kernel<<<dim3(SS/64, BB*HH), 256>>>(vp, vthi, vtlo);

    attn_bf3_kernel<<<dim3(SS/64, BB*HH), 128, ATTN_SMEM>>>(
        qhi, qlo, khi, klo, vthi, vtlo, ahi, alo);

    gemm_bf3_kernel<<<ggrid, 256, GEMM_SMEM>>>(ahi, alo, wh + 3*(size_t)NW, wl + 3*(size_t)NW,
                                               bo, nullptr, nullptr, out, nullptr, nullptr, 0);
}

// round 8
// speedup vs baseline: 5.6183x; 1.0677x over previous
#include <cuda_runtime.h>
#include <cuda_bf16.h>
#include <stdint.h>

// Problem constants
#define BB 4
#define SS 2048
#define DD 1024
#define HH 16
#define HD 64
#define BS (BB*SS)
#define NQ (BB*HH*SS*HD)
#define NX (BS*DD)
#define NW (DD*DD)

// ---------------------------------------------------------------------------
// Static device scratch
// ---------------------------------------------------------------------------
__device__ __nv_bfloat16 g_xhi[NX],  g_xlo[NX];
__device__ __nv_bfloat16 g_ahi[NX],  g_alo[NX];       // attention out hi/lo
__device__ __nv_bfloat16 g_qhi[NQ],  g_qlo[NQ];
__device__ __nv_bfloat16 g_khi[NQ],  g_klo[NQ];
__device__ __nv_bfloat16 g_vthi[NQ], g_vtlo[NQ];      // [B,H,HD,S]
__device__ __nv_bfloat16 g_wh[4][NW], g_wl[4][NW];

// ---------------------------------------------------------------------------
// helpers
// ---------------------------------------------------------------------------
__device__ __forceinline__ uint32_t pack_bf2(float a, float b) {
    __nv_bfloat16 ha = __float2bfloat16(a), hb = __float2bfloat16(b);
    unsigned short ua = *reinterpret_cast<unsigned short*>(&ha);
    unsigned short ub = *reinterpret_cast<unsigned short*>(&hb);
    return (uint32_t)ua | ((uint32_t)ub << 16);
}
__device__ __forceinline__ float bf_res(float x) {
    __nv_bfloat16 h = __float2bfloat16(x);
    return x - __bfloat162float(h);
}

__device__ __forceinline__ void mma_bf16(float* c, const uint32_t* a,
                                         uint32_t b0, uint32_t b1)
{
    asm("mma.sync.aligned.m16n8k16.row.col.f32.bf16.bf16.f32 "
        "{%0,%1,%2,%3},{%4,%5,%6,%7},{%8,%9},{%0,%1,%2,%3};"
        : "+f"(c[0]), "+f"(c[1]), "+f"(c[2]), "+f"(c[3])
        : "r"(a[0]), "r"(a[1]), "r"(a[2]), "r"(a[3]), "r"(b0), "r"(b1));
}

__device__ __forceinline__ void ldsm_x4(uint32_t* r, uint32_t addr) {
    asm volatile("ldmatrix.sync.aligned.m8n8.x4.shared.b16 {%0,%1,%2,%3}, [%4];"
        : "=r"(r[0]), "=r"(r[1]), "=r"(r[2]), "=r"(r[3]) : "r"(addr));
}

#define CP16(dst_smem_u32, src_gptr) \
    asm volatile("cp.async.cg.shared.global [%0], [%1], 16;\n" \
                 :: "r"(dst_smem_u32), "l"(src_gptr))
#define CP_COMMIT() asm volatile("cp.async.commit_group;\n")
#define CP_WAIT1()  asm volatile("cp.async.wait_group 1;\n")
#define CP_WAIT0()  asm volatile("cp.async.wait_group 0;\n")

// ---------------------------------------------------------------------------
// split fp32 -> bf16 hi/lo  (x)
// ---------------------------------------------------------------------------
__global__ __launch_bounds__(256) void split4_kernel(
    const float* __restrict__ in, __nv_bfloat16* __restrict__ hi,
    __nv_bfloat16* __restrict__ lo, int n4)
{
    int i = blockIdx.x * blockDim.x + threadIdx.x;
    if (i >= n4) return;
    float4 v = ((const float4*)in)[i];
    ((uint2*)hi)[i] = make_uint2(pack_bf2(v.x, v.y), pack_bf2(v.z, v.w));
    ((uint2*)lo)[i] = make_uint2(pack_bf2(bf_res(v.x), bf_res(v.y)),
                                 pack_bf2(bf_res(v.z), bf_res(v.w)));
}

// all 4 weights in one launch: blockIdx.y selects the weight
__global__ __launch_bounds__(256) void splitW_kernel(
    const float* __restrict__ W0, const float* __restrict__ W1,
    const float* __restrict__ W2, const float* __restrict__ W3,
    __nv_bfloat16* __restrict__ wh, __nv_bfloat16* __restrict__ wl)
{
    const int z = blockIdx.y;
    const float* src = (z == 0) ? W0 : (z == 1) ? W1 : (z == 2) ? W2 : W3;
    const int i = blockIdx.x * blockDim.x + threadIdx.x;   // < NW/4
    float4 v = ((const float4*)src)[i];
    const size_t o = (size_t)z * (NW/4) + i;
    ((uint2*)wh)[o] = make_uint2(pack_bf2(v.x, v.y), pack_bf2(v.z, v.w));
    ((uint2*)wl)[o] = make_uint2(pack_bf2(bf_res(v.x), bf_res(v.y)),
                                 pack_bf2(bf_res(v.z), bf_res(v.w)));
}

// ---------------------------------------------------------------------------
// shared bf16x3 GEMM mainloop: acc[2][8][4] = A[128,1024] . W^T tile
// ---------------------------------------------------------------------------
#define RST 20
#define OPB (128*RST)
#define GEMM_SMEM (8*OPB*4)

__device__ __forceinline__ void gemm_mainloop(
    const __nv_bfloat16* __restrict__ Ah, const __nv_bfloat16* __restrict__ Al,
    const __nv_bfloat16* __restrict__ Wh, const __nv_bfloat16* __restrict__ Wl,
    int m0, int n0, uint32_t smb, int tid, float acc[2][8][4])
{
    const int lane = tid & 31;
    const int w    = tid >> 5;
    const int wm   = (w & 3) * 32;
    const int wn   = (w >> 2) * 64;
    const uint32_t aoff = (uint32_t)(((((lane>>3)&1)*8 + (lane&7))*RST + ((lane>>4)*4)) * 4);
    const uint32_t boff = (uint32_t)((((lane>>4)*8 + (lane&7))*RST + (((lane>>3)&1)*4)) * 4);

    const int NK = DD / 32;

    #define LOAD_STAGE(kt, stg) do {                                          \
        uint32_t sb_ = smb + (stg)*4*OPB*4;                                   \
        _Pragma("unroll")                                                     \
        for (int i_ = 0; i_ < 2; i_++) {                                      \
            int c_ = tid + 256*i_;                                            \
            int row_ = c_ >> 2, col16_ = c_ & 3;                              \
            uint32_t so_ = sb_ + (uint32_t)((row_*RST + col16_*4)*4);         \
            size_t ga_ = (size_t)(m0+row_)*DD + (kt)*32 + col16_*8;           \
            size_t gw_ = (size_t)(n0+row_)*DD + (kt)*32 + col16_*8;           \
            CP16(so_,           Ah + ga_);                                    \
            CP16(so_ + OPB*4,   Al + ga_);                                    \
            CP16(so_ + 2*OPB*4, Wh + gw_);                                    \
            CP16(so_ + 3*OPB*4, Wl + gw_);                                    \
        }                                                                     \
        CP_COMMIT();                                                          \
    } while (0)

    LOAD_STAGE(0, 0);

    for (int it = 0; it < NK; it++) {
        if (it + 1 < NK) {
            LOAD_STAGE(it + 1, (it + 1) & 1);
            CP_WAIT1();
        } else {
            CP_WAIT0();
        }
        __syncthreads();

        const uint32_t sb  = smb + (it & 1)*4*OPB*4;
        const uint32_t ahB = sb;
        const uint32_t alB = sb + OPB*4;
        const uint32_t whB = sb + 2*OPB*4;
        const uint32_t wlB = sb + 3*OPB*4;

        #pragma unroll
        for (int s16 = 0; s16 < 2; s16++) {
            const uint32_t kbyte = s16 * 32;
            uint32_t ah[2][4], al[2][4];
            #pragma unroll
            for (int mt = 0; mt < 2; mt++) {
                const uint32_t ro = (uint32_t)((wm + mt*16)*RST*4);
                ldsm_x4(ah[mt], ahB + aoff + ro + kbyte);
                ldsm_x4(al[mt], alB + aoff + ro + kbyte);
            }
            #pragma unroll
            for (int ntp = 0; ntp < 4; ntp++) {
                const uint32_t ro = (uint32_t)((wn + ntp*16)*RST*4);
                uint32_t wh4[4], wl4[4];
                ldsm_x4(wh4, whB + boff + ro + kbyte);
                ldsm_x4(wl4, wlB + boff + ro + kbyte);
                #pragma unroll
                for (int j = 0; j < 2; j++) {
                    const int nt = 2*ntp + j;
                    const uint32_t bh0 = wh4[2*j], bh1 = wh4[2*j+1];
                    const uint32_t bl0 = wl4[2*j], bl1 = wl4[2*j+1];
                    #pragma unroll
                    for (int mt = 0; mt < 2; mt++) {
                        mma_bf16(acc[mt][nt], ah[mt], bh0, bh1);
                        mma_bf16(acc[mt][nt], ah[mt], bl0, bl1);
                        mma_bf16(acc[mt][nt], al[mt], bh0, bh1);
                    }
                }
            }
        }
        __syncthreads();
    }
    #undef LOAD_STAGE
}

// ---------------------------------------------------------------------------
// QKV merged GEMM: grid.z = 0(Q rope), 1(K rope), 2(V transpose-split)
// ---------------------------------------------------------------------------
__global__ __launch_bounds__(256, 2) void gemm_qkv_kernel(
    const __nv_bfloat16* __restrict__ Ah, const __nv_bfloat16* __restrict__ Al,
    const __nv_bfloat16* __restrict__ whAll, const __nv_bfloat16* __restrict__ wlAll,
    const float* __restrict__ bq, const float* __restrict__ bk,
    const float* __restrict__ bv,
    const float* __restrict__ cosb, const float* __restrict__ sinb,
    __nv_bfloat16* __restrict__ Qhi, __nv_bfloat16* __restrict__ Qlo,
    __nv_bfloat16* __restrict__ Khi, __nv_bfloat16* __restrict__ Klo,
    __nv_bfloat16* __restrict__ Vthi, __nv_bfloat16* __restrict__ Vtlo)
{
    extern __shared__ uint32_t su[];
    const uint32_t smb = (uint32_t)__cvta_generic_to_shared(su);
    const int tid = threadIdx.x;
    const int m0  = blockIdx.y * 128;
    const int n0  = blockIdx.x * 128;
    const int z   = blockIdx.z;

    const __nv_bfloat16* Wh = whAll + (size_t)z * NW;
    const __nv_bfloat16* Wl = wlAll + (size_t)z * NW;
    const float* bias = (z == 0) ? bq : (z == 1) ? bk : bv;

    float acc[2][8][4];
    #pragma unroll
    for (int mt = 0; mt < 2; mt++)
        #pragma unroll
        for (int nt = 0; nt < 8; nt++)
            #pragma unroll
            for (int r = 0; r < 4; r++) acc[mt][nt][r] = 0.f;

    gemm_mainloop(Ah, Al, Wh, Wl, m0, n0, smb, tid, acc);

    const int lane = tid & 31;
    const int w    = tid >> 5;
    const int g    = lane >> 2;
    const int q    = lane & 3;
    const int wm   = (w & 3) * 32;
    const int wn   = (w >> 2) * 64;

    if (z < 2) {
        // rope + split, head-major bf16 hi/lo
        __nv_bfloat16* ChiT = (z == 0) ? Qhi : Khi;
        __nv_bfloat16* CloT = (z == 0) ? Qlo : Klo;
        uint32_t* HI = (uint32_t*)ChiT;
        uint32_t* LO = (uint32_t*)CloT;
        #pragma unroll
        for (int mt = 0; mt < 2; mt++) {
            const int row0 = m0 + wm + mt*16 + g;
            #pragma unroll
            for (int nt = 0; nt < 4; nt++) {
                const int col = n0 + wn + nt*8 + 2*q;
                const int d = col & 63, h = col >> 6;
                const float bi10 = bias[col],    bi11 = bias[col+1];
                const float bi20 = bias[col+32], bi21 = bias[col+33];
                #pragma unroll
                for (int r2 = 0; r2 < 2; r2++) {
                    const int row = row0 + r2*8;
                    const int b_ = row >> 11, s_ = row & 2047;
                    const float2 cs1 = *(const float2*)&cosb[s_*HD + d];
                    const float2 sn1 = *(const float2*)&sinb[s_*HD + d];
                    const float2 cs2 = *(const float2*)&cosb[s_*HD + d + 32];
                    const float2 sn2 = *(const float2*)&sinb[s_*HD + d + 32];
                    const float x10 = acc[mt][nt  ][r2*2+0] + bi10;
                    const float x11 = acc[mt][nt  ][r2*2+1] + bi11;
                    const float x20 = acc[mt][nt+4][r2*2+0] + bi20;
                    const float x21 = acc[mt][nt+4][r2*2+1] + bi21;
                    const float o10 = x10*cs1.x - x20*sn1.x;
                    const float o11 = x11*cs1.y - x21*sn1.y;
                    const float o20 = x20*cs2.x + x10*sn2.x;
                    const float o21 = x21*cs2.y + x11*sn2.y;
                    const size_t base = (((size_t)b_*HH + h)*SS + s_)*HD;
                    HI[(base + d     ) >> 1] = pack_bf2(o10, o11);
                    LO[(base + d     ) >> 1] = pack_bf2(bf_res(o10), bf_res(o11));
                    HI[(base + d + 32) >> 1] = pack_bf2(o20, o21);
                    LO[(base + d + 32) >> 1] = pack_bf2(bf_res(o20), bf_res(o21));
                }
            }
        }
    } else {
        // V: direct transposed split write [B,H,HD,S]
        #pragma unroll
        for (int mt = 0; mt < 2; mt++) {
            const int row0 = m0 + wm + mt*16 + g;
            #pragma unroll
            for (int nt = 0; nt < 8; nt++) {
                const int col = n0 + wn + nt*8 + 2*q;   // even
                const int h = col >> 6, d = col & 63;
                const float b0 = bias[col], b1 = bias[col+1];
                #pragma unroll
                for (int r2 = 0; r2 < 2; r2++) {
                    const int row = row0 + r2*8;
                    const int b_ = row >> 11, s_ = row & 2047;
                    const float v0 = acc[mt][nt][r2*2+0] + b0;
                    const float v1 = acc[mt][nt][r2*2+1] + b1;
                    const size_t base0 = (((size_t)b_*HH + h)*HD + d)*SS + s_;
                    Vthi[base0]      = __float2bfloat16(v0);
                    Vtlo[base0]      = __float2bfloat16(bf_res(v0));
                    Vthi[base0 + SS] = __float2bfloat16(v1);
                    Vtlo[base0 + SS] = __float2bfloat16(bf_res(v1));
                }
            }
        }
    }
}

// ---------------------------------------------------------------------------
// Output-projection GEMM: plain fp32 out [M,N]
// ---------------------------------------------------------------------------
__global__ __launch_bounds__(256, 2) void gemm_out_kernel(
    const __nv_bfloat16* __restrict__ Ah, const __nv_bfloat16* __restrict__ Al,
    const __nv_bfloat16* __restrict__ Wh, const __nv_bfloat16* __restrict__ Wl,
    const float* __restrict__ bias, float* __restrict__ Cf)
{
    extern __shared__ uint32_t su[];
    const uint32_t smb = (uint32_t)__cvta_generic_to_shared(su);
    const int tid = threadIdx.x;
    const int m0  = blockIdx.y * 128;
    const int n0  = blockIdx.x * 128;

    float acc[2][8][4];
    #pragma unroll
    for (int mt = 0; mt < 2; mt++)
        #pragma unroll
        for (int nt = 0; nt < 8; nt++)
            #pragma unroll
            for (int r = 0; r < 4; r++) acc[mt][nt][r] = 0.f;

    gemm_mainloop(Ah, Al, Wh, Wl, m0, n0, smb, tid, acc);

    const int lane = tid & 31;
    const int w    = tid >> 5;
    const int g    = lane >> 2;
    const int q    = lane & 3;
    const int wm   = (w & 3) * 32;
    const int wn   = (w >> 2) * 64;

    #pragma unroll
    for (int mt = 0; mt < 2; mt++) {
        const int row0 = m0 + wm + mt*16 + g;
        const int row1 = row0 + 8;
        #pragma unroll
        for (int nt = 0; nt < 8; nt++) {
            const int col = n0 + wn + nt*8 + 2*q;
            const float b0 = bias[col], b1 = bias[col + 1];
            *(float2*)&Cf[(size_t)row0*DD + col] =
                make_float2(acc[mt][nt][0] + b0, acc[mt][nt][1] + b1);
            *(float2*)&Cf[(size_t)row1*DD + col] =
                make_float2(acc[mt][nt][2] + b0, acc[mt][nt][3] + b1);
        }
    }
}

// ---------------------------------------------------------------------------
// FlashAttention-2 (causal), bf16x3, ldmatrix + register-P + cp.async
// double-buffered KV tiles. 4 warps, 64 q-rows/block, KV tiles 64.
// ---------------------------------------------------------------------------
#define KST 36
#define ATILE (64*KST)
#define ASTG  (4*ATILE)
#define ATTN_SMEM (2*ASTG*4)

__device__ __forceinline__ void attn_prefetch(
    uint32_t sstage,
    const __nv_bfloat16* __restrict__ Kh, const __nv_bfloat16* __restrict__ Kl,
    const __nv_bfloat16* __restrict__ Vth, const __nv_bfloat16* __restrict__ Vtl,
    size_t hb, int bh, int k0, int tid)
{
    #pragma unroll
    for (int i = 0; i < 4; i++) {
        int c = tid + 128*i;
        int row = c >> 3, c16 = c & 7;
        uint32_t so = sstage + (uint32_t)((row*KST + c16*4)*4);
        size_t ko = hb + (size_t)(k0 + row)*HD + c16*8;
        CP16(so,             Kh + ko);
        CP16(so + ATILE*4,   Kl + ko);
        size_t vo = ((size_t)bh*HD + row)*SS + k0 + c16*8;
        CP16(so + 2*ATILE*4, Vth + vo);
        CP16(so + 3*ATILE*4, Vtl + vo);
    }
    CP_COMMIT();
}

__global__ __launch_bounds__(128) void attn_bf3_kernel(
    const __nv_bfloat16* __restrict__ Qh, const __nv_bfloat16* __restrict__ Ql,
    const __nv_bfloat16* __restrict__ Kh, const __nv_bfloat16* __restrict__ Kl,
    const __nv_bfloat16* __restrict__ Vth, const __nv_bfloat16* __restrict__ Vtl,
    __nv_bfloat16* __restrict__ OutHi, __nv_bfloat16* __restrict__ OutLo)
{
    extern __shared__ uint32_t su[];
    const uint32_t smb = (uint32_t)__cvta_generic_to_shared(su);

    const int tid  = threadIdx.x;
    const int w    = tid >> 5;
    const int lane = tid & 31;
    const int g    = lane >> 2;
    const int q    = lane & 3;
    const int qt   = (SS/64 - 1) - blockIdx.x;
    const int bh   = blockIdx.y;
    const int q0   = qt * 64;
    const size_t hb = (size_t)bh * SS * HD;

    const uint32_t aoff = (uint32_t)(((((lane>>3)&1)*8 + (lane&7))*KST + ((lane>>4)*4)) * 4);
    const uint32_t boff = (uint32_t)((((lane>>4)*8 + (lane&7))*KST + (((lane>>3)&1)*4)) * 4);

    #pragma unroll
    for (int i = 0; i < 4; i++) {
        int c = tid + 128*i;
        int row = c >> 3, c16 = c & 7;
        uint32_t so = smb + ASTG*4 + (uint32_t)((row*KST + c16*4)*4);
        size_t go = hb + (size_t)(q0 + row)*HD + c16*8;
        CP16(so,           Qh + go);
        CP16(so + ATILE*4, Ql + go);
    }
    CP_COMMIT();
    attn_prefetch(smb, Kh, Kl, Vth, Vtl, hb, bh, 0, tid);

    CP_WAIT1();
    __syncthreads();

    const int rb = 16*w;
    uint32_t rQh[4][4], rQl[4][4];
    #pragma unroll
    for (int ks = 0; ks < 4; ks++) {
        const uint32_t ro = (uint32_t)(rb*KST*4) + ks*32;
        ldsm_x4(rQh[ks], smb + ASTG*4 + aoff + ro);
        ldsm_x4(rQl[ks], smb + ASTG*4 + ATILE*4 + aoff + ro);
    }
    __syncthreads();
    if (qt > 0)
        attn_prefetch(smb + ASTG*4, Kh, Kl, Vth, Vtl, hb, bh, 64, tid);

    float oc[8][4];
    #pragma unroll
    for (int nt = 0; nt < 8; nt++)
        #pragma unroll
        for (int r = 0; r < 4; r++) oc[nt][r] = 0.f;
    float m0 = -1e30f, m1 = -1e30f, l0 = 0.f, l1 = 0.f;

    const int row0g = q0 + 16*w + g;
    const int row1g = row0g + 8;

    for (int kt = 0; kt <= qt; kt++) {
        const int k0 = kt * 64;
        const uint32_t ab   = smb + (kt & 1)*ASTG*4;
        const uint32_t aKsH = ab;
        const uint32_t aKsL = ab + ATILE*4;
        const uint32_t aVsH = ab + 2*ATILE*4;
        const uint32_t aVsL = ab + 3*ATILE*4;

        if (kt < qt) { CP_WAIT1(); } else { CP_WAIT0(); }
        __syncthreads();

        float sc[8][4];
        #pragma unroll
        for (int nt = 0; nt < 8; nt++)
            #pragma unroll
            for (int r = 0; r < 4; r++) sc[nt][r] = 0.f;

        #pragma unroll
        for (int ks = 0; ks < 4; ks++) {
            const uint32_t kbyte = ks*32;
            #pragma unroll
            for (int ntp = 0; ntp < 4; ntp++) {
                const uint32_t ro = (uint32_t)(ntp*16*KST*4) + kbyte;
                uint32_t kh4[4], kl4[4];
                ldsm_x4(kh4, aKsH + boff + ro);
                ldsm_x4(kl4, aKsL + boff + ro);
                #pragma unroll
                for (int j = 0; j < 2; j++) {
                    const int nt = 2*ntp + j;
                    mma_bf16(sc[nt], rQh[ks], kh4[2*j], kh4[2*j+1]);
                    mma_bf16(sc[nt], rQh[ks], kl4[2*j], kl4[2*j+1]);
                    mma_bf16(sc[nt], rQl[ks], kh4[2*j], kh4[2*j+1]);
                }
            }
        }

        const float scale = 0.125f;
        const bool diag = (kt == qt);
        #pragma unroll
        for (int nt = 0; nt < 8; nt++) {
            const int colb = k0 + nt*8 + 2*q;
            #pragma unroll
            for (int j = 0; j < 2; j++) {
                float v0 = sc[nt][j]   * scale;
                float v1 = sc[nt][2+j] * scale;
                if (diag && (colb + j) > row0g) v0 = -1e30f;
                if (diag && (colb + j) > row1g) v1 = -1e30f;
                sc[nt][j]   = v0;
                sc[nt][2+j] = v1;
            }
        }

        float mx0 = -1e30f, mx1 = -1e30f;
        #pragma unroll
        for (int nt = 0; nt < 8; nt++) {
            mx0 = fmaxf(mx0, fmaxf(sc[nt][0], sc[nt][1]));
            mx1 = fmaxf(mx1, fmaxf(sc[nt][2], sc[nt][3]));
        }
        mx0 = fmaxf(mx0, __shfl_xor_sync(0xffffffffu, mx0, 1));
        mx0 = fmaxf(mx0, __shfl_xor_sync(0xffffffffu, mx0, 2));
        mx1 = fmaxf(mx1, __shfl_xor_sync(0xffffffffu, mx1, 1));
        mx1 = fmaxf(mx1, __shfl_xor_sync(0xffffffffu, mx1, 2));
        const float mn0 = fmaxf(m0, mx0);
        const float mn1 = fmaxf(m1, mx1);
        const float a0 = __expf(m0 - mn0);
        const float a1 = __expf(m1 - mn1);
        m0 = mn0; m1 = mn1;

        uint32_t ph[8][2], pl[8][2];
        float s0 = 0.f, s1 = 0.f;
        #pragma unroll
        for (int nt = 0; nt < 8; nt++) {
            float p00 = __expf(sc[nt][0] - mn0);
            float p01 = __expf(sc[nt][1] - mn0);
            float p10 = __expf(sc[nt][2] - mn1);
            float p11 = __expf(sc[nt][3] - mn1);
            s0 += p00 + p01;
            s1 += p10 + p11;
            ph[nt][0] = pack_bf2(p00, p01);
            ph[nt][1] = pack_bf2(p10, p11);
            pl[nt][0] = pack_bf2(bf_res(p00), bf_res(p01));
            pl[nt][1] = pack_bf2(bf_res(p10), bf_res(p11));
        }
        s0 += __shfl_xor_sync(0xffffffffu, s0, 1);
        s0 += __shfl_xor_sync(0xffffffffu, s0, 2);
        s1 += __shfl_xor_sync(0xffffffffu, s1, 1);
        s1 += __shfl_xor_sync(0xffffffffu, s1, 2);
        l0 = l0*a0 + s0;
        l1 = l1*a1 + s1;
        #pragma unroll
        for (int nt = 0; nt < 8; nt++) {
            oc[nt][0] *= a0; oc[nt][1] *= a0;
            oc[nt][2] *= a1; oc[nt][3] *= a1;
        }

        #pragma unroll
        for (int kc = 0; kc < 4; kc++) {
            uint32_t ah4[4] = { ph[2*kc][0], ph[2*kc][1], ph[2*kc+1][0], ph[2*kc+1][1] };
            uint32_t al4[4] = { pl[2*kc][0], pl[2*kc][1], pl[2*kc+1][0], pl[2*kc+1][1] };
            const uint32_t kbyte = kc*32;
            #pragma unroll
            for (int ntp = 0; ntp < 4; ntp++) {
                const uint32_t ro = (uint32_t)(ntp*16*KST*4) + kbyte;
                uint32_t vh4[4], vl4[4];
                ldsm_x4(vh4, aVsH + boff + ro);
                ldsm_x4(vl4, aVsL + boff + ro);
                #pragma unroll
                for (int j = 0; j < 2; j++) {
                    const int nto = 2*ntp + j;
                    mma_bf16(oc[nto], ah4, vh4[2*j], vh4[2*j+1]);
                    mma_bf16(oc[nto], ah4, vl4[2*j], vl4[2*j+1]);
                    mma_bf16(oc[nto], al4, vh4[2*j], vh4[2*j+1]);
                }
            }
        }

        __syncthreads();
        if (kt + 2 <= qt)
            attn_prefetch(ab, Kh, Kl, Vth, Vtl, hb, bh, (kt + 2)*64, tid);
    }

    const float i0 = 1.f / l0;
    const float i1 = 1.f / l1;
    const int b = bh >> 4;
    const int h = bh & 15;
    const size_t o0 = ((size_t)(b*SS + row0g))*DD + h*HD;
    const size_t o1 = ((size_t)(b*SS + row1g))*DD + h*HD;
    uint32_t* HI = (uint32_t*)OutHi;
    uint32_t* LO = (uint32_t*)OutLo;
    #pragma unroll
    for (int nt = 0; nt < 8; nt++) {
        const int col = nt*8 + 2*q;
        const float v00 = oc[nt][0]*i0, v01 = oc[nt][1]*i0;
        const float v10 = oc[nt][2]*i1, v11 = oc[nt][3]*i1;
        HI[(o0 + col) >> 1] = pack_bf2(v00, v01);
        LO[(o0 + col) >> 1] = pack_bf2(bf_res(v00), bf_res(v01));
        HI[(o1 + col) >> 1] = pack_bf2(v10, v11);
        LO[(o1 + col) >> 1] = pack_bf2(bf_res(v10), bf_res(v11));
    }
}

// ---------------------------------------------------------------------------
// Launch: splitx, splitW, gemmQKV, attn, gemmOut  (5 launches; #5 profiled)
// ---------------------------------------------------------------------------
extern "C" void kernel_launch(void* const* d_in, const int* in_sizes, int n_in,
                              void* d_out, int out_size)
{
    const float* x    = (const float*)d_in[0];
    const float* cosb = (const float*)d_in[1];
    const float* sinb = (const float*)d_in[2];
    const float* Wq = (const float*)d_in[4];
    const float* bq = (const float*)d_in[5];
    const float* Wk = (const float*)d_in[6];
    const float* bk = (const float*)d_in[7];
    const float* Wv = (const float*)d_in[8];
    const float* bv = (const float*)d_in[9];
    const float* Wo = (const float*)d_in[10];
    const float* bo = (const float*)d_in[11];
    float* out = (float*)d_out;

    __nv_bfloat16 *xhi, *xlo, *ahi, *alo, *qhi, *qlo, *khi, *klo, *vthi, *vtlo;
    __nv_bfloat16 *wh, *wl;
    cudaGetSymbolAddress((void**)&xhi,  g_xhi);
    cudaGetSymbolAddress((void**)&xlo,  g_xlo);
    cudaGetSymbolAddress((void**)&ahi,  g_ahi);
    cudaGetSymbolAddress((void**)&alo,  g_alo);
    cudaGetSymbolAddress((void**)&qhi,  g_qhi);
    cudaGetSymbolAddress((void**)&qlo,  g_qlo);
    cudaGetSymbolAddress((void**)&khi,  g_khi);
    cudaGetSymbolAddress((void**)&klo,  g_klo);
    cudaGetSymbolAddress((void**)&vthi, g_vthi);
    cudaGetSymbolAddress((void**)&vtlo, g_vtlo);
    cudaGetSymbolAddress((void**)&wh,   g_wh);
    cudaGetSymbolAddress((void**)&wl,   g_wl);

    cudaFuncSetAttribute(gemm_qkv_kernel,
                         cudaFuncAttributeMaxDynamicSharedMemorySize, GEMM_SMEM);
    cudaFuncSetAttribute(gemm_out_kernel,
                         cudaFuncAttributeMaxDynamicSharedMemorySize, GEMM_SMEM);
    cudaFuncSetAttribute(attn_bf3_kernel,
                         cudaFuncAttributeMaxDynamicSharedMemorySize, ATTN_SMEM);

    // 1: split x
    split4_kernel<<<NX/4/256, 256>>>(x, xhi, xlo, NX/4);
    // 2: split all 4 weights
    splitW_kernel<<<dim3(NW/4/256, 4), 256>>>(Wq, Wk, Wv, Wo, wh, wl);
    // 3: QKV projections (merged; rope fused for Q,K; transpose-split for V)
    gemm_qkv_kernel<<<dim3(DD/128, BS/128, 3), 256, GEMM_SMEM>>>(
        xhi, xlo, wh, wl, bq, bk, bv, cosb, sinb,
        qhi, qlo, khi, klo, vthi, vtlo);
    // 4: attention
    attn_bf3_kernel<<<dim3(SS/64, BB*HH), 128, ATTN_SMEM>>>(
        qhi, qlo, khi, klo, vthi, vtlo, ahi, alo);
    // 5: output projection (this launch gets ncu-profiled)
    gemm_out_kernel<<<dim3(DD/128, BS/128), 256, GEMM_SMEM>>>(
        ahi, alo, wh + 3*(size_t)NW, wl + 3*(size_t)NW, bo, out);
}